// round 7
// baseline (speedup 1.0000x reference)
#include <cuda_runtime.h>
#include <cuda_fp16.h>
#include <math.h>

// GATv2 (L=3, H=4, C=16, D=64), N=100000, E=1280000 (+N self loops).
// R7:
//  - agg = R4 shape (warp = 2 nodes x 16 channel-lanes, 4 ch/lane) but the edge
//    loop runs in fully-unrolled 16-edge chunks: 16 broadcasts + 16 batched
//    LDG.64 (MLP=16), predicated padding (flag*exp), fp32 logits.
//  - launch order puts k_agg at launch index 5 for ncu (-s 5 -c 1):
//    gemm, hist, scan1(self-zeroing), scan23(fused), scatter, agg, ...

#define NNODES 100000
#define NEDGES 1280000
#define DD 64
#define SCAN_BLK 512
#define SCAN_ELEM 8
#define SCAN_TILE (SCAN_BLK * SCAN_ELEM)  // 4096

__device__ __align__(128) __half g_xlh[NNODES * DD];
__device__ __align__(16) float g_xr[NNODES * DD];
__device__ __align__(16) float g_b0[NNODES * DD];
__device__ __align__(16) float g_b1[NNODES * DD];
__device__ int g_cnt[NNODES];      // zero-init at load; scan1 re-zeroes each run
__device__ int g_tmp[NNODES];
__device__ int g_ofs[NNODES];
__device__ int g_rowptr[NNODES + 1];
__device__ int g_bsum[32];
__device__ int g_ssrc[NEDGES];

// ------------------------- CSR build (once per launch) ----------------------
__global__ void k_hist(const int* __restrict__ ei, int E) {
    int e = blockIdx.x * blockDim.x + threadIdx.x;
    if (e < E) atomicAdd(&g_cnt[ei[E + e]], 1);
}

// Per-block scan of g_cnt; ALSO zeroes g_cnt for the next graph replay.
__global__ __launch_bounds__(SCAN_BLK) void k_scan1(int n) {
    __shared__ int sh[SCAN_BLK];
    int blk = blockIdx.x;
    int base = blk * SCAN_TILE + threadIdx.x * SCAN_ELEM;
    int t = threadIdx.x;
    int v[SCAN_ELEM];
    int sum = 0;
#pragma unroll
    for (int i = 0; i < SCAN_ELEM; i++) {
        int idx = base + i;
        v[i] = (idx < n) ? g_cnt[idx] : 0;
        if (idx < n) g_cnt[idx] = 0;
        sum += v[i];
    }
    sh[t] = sum;
    __syncthreads();
    for (int o = 1; o < SCAN_BLK; o <<= 1) {
        int x = (t >= o) ? sh[t - o] : 0;
        __syncthreads();
        sh[t] += x;
        __syncthreads();
    }
    int run = (t > 0) ? sh[t - 1] : 0;
    if (t == SCAN_BLK - 1) g_bsum[blk] = sh[t];
#pragma unroll
    for (int i = 0; i < SCAN_ELEM; i++) {
        int idx = base + i;
        if (idx < n) g_tmp[idx] = run;
        run += v[i];
    }
}

// Fused: scan of (<=32) block sums done redundantly per block, then add.
__global__ void k_scan23(int n, int E, int nb) {
    __shared__ int pre[33];
    if (threadIdx.x == 0) {
        int run = 0;
        for (int b = 0; b < nb; b++) { pre[b] = run; run += g_bsum[b]; }
    }
    __syncthreads();
    int i = blockIdx.x * blockDim.x + threadIdx.x;
    if (i < n) {
        int r = g_tmp[i] + pre[i / SCAN_TILE];
        g_rowptr[i] = r;
        g_ofs[i] = r;
    }
    if (i == n) g_rowptr[n] = E;
}

__global__ void k_scatter(const int* __restrict__ ei, int E) {
    int e = blockIdx.x * blockDim.x + threadIdx.x;
    if (e < E) {
        int d = ei[E + e];
        int pos = atomicAdd(&g_ofs[d], 1);
        g_ssrc[pos] = ei[e];
    }
}

// ---------------------------------------------------------------------------
// GEMM: xl = x @ Wl (-> fp16), xr = x @ Wr (-> fp32).  K = 64.
// ---------------------------------------------------------------------------
__global__ __launch_bounds__(256) void k_gemm(const float* __restrict__ x,
                                              const float* __restrict__ Wl,
                                              const float* __restrict__ Wr,
                                              int n) {
    __shared__ float sWl[64][64];
    __shared__ float sWr[64][64];
    __shared__ float sxT[64][64];

    int nodeBase = blockIdx.x * 64;

    for (int i = threadIdx.x; i < 64 * 64; i += 256) {
        sWl[i >> 6][i & 63] = Wl[i];
        sWr[i >> 6][i & 63] = Wr[i];
        int r = i >> 6, c = i & 63;
        int node = nodeBase + r;
        float v = (node < n) ? x[(size_t)node * DD + c] : 0.f;
        sxT[c][r] = v;
    }
    __syncthreads();

    int local = threadIdx.x >> 2;
    int cg = (threadIdx.x & 3) << 4;

    float accL[16], accR[16];
#pragma unroll
    for (int c = 0; c < 16; c++) { accL[c] = 0.f; accR[c] = 0.f; }

#pragma unroll 4
    for (int k = 0; k < 64; k++) {
        float xv = sxT[k][local];
        const float4* wl = (const float4*)&sWl[k][cg];
        const float4* wr = (const float4*)&sWr[k][cg];
#pragma unroll
        for (int q = 0; q < 4; q++) {
            float4 a = wl[q];
            float4 b = wr[q];
            accL[q * 4 + 0] = fmaf(xv, a.x, accL[q * 4 + 0]);
            accL[q * 4 + 1] = fmaf(xv, a.y, accL[q * 4 + 1]);
            accL[q * 4 + 2] = fmaf(xv, a.z, accL[q * 4 + 2]);
            accL[q * 4 + 3] = fmaf(xv, a.w, accL[q * 4 + 3]);
            accR[q * 4 + 0] = fmaf(xv, b.x, accR[q * 4 + 0]);
            accR[q * 4 + 1] = fmaf(xv, b.y, accR[q * 4 + 1]);
            accR[q * 4 + 2] = fmaf(xv, b.z, accR[q * 4 + 2]);
            accR[q * 4 + 3] = fmaf(xv, b.w, accR[q * 4 + 3]);
        }
    }

    int node = nodeBase + local;
    if (node < n) {
        __half2 hh[8];
#pragma unroll
        for (int q = 0; q < 8; q++)
            hh[q] = __floats2half2_rn(accL[2 * q], accL[2 * q + 1]);
        *(uint4*)&g_xlh[(size_t)node * DD + cg] = *(uint4*)&hh[0];
        *(uint4*)&g_xlh[(size_t)node * DD + cg + 8] = *(uint4*)&hh[4];

        float4* outr = (float4*)&g_xr[(size_t)node * DD + cg];
#pragma unroll
        for (int q = 0; q < 4; q++)
            outr[q] = make_float4(accR[q * 4 + 0], accR[q * 4 + 1], accR[q * 4 + 2], accR[q * 4 + 3]);
    }
}

// ---------------------------------------------------------------------------
// Fused aggregation: warp = 2 nodes x 16 lanes, 4 channels/lane.
// Edge loop in fully-unrolled 16-edge chunks (batched LDGs, MLP=16).
// ---------------------------------------------------------------------------
__global__ __launch_bounds__(256) void k_agg(const float* __restrict__ xres,
                                             const float* __restrict__ att,
                                             const float* __restrict__ bias,
                                             const float* __restrict__ gamma,
                                             const float* __restrict__ beta,
                                             float* __restrict__ out, int n) {
    int warp = (blockIdx.x * blockDim.x + threadIdx.x) >> 5;
    int lane = threadIdx.x & 31;
    int h = lane >> 4;
    int l16 = lane & 15;
    int d = warp * 2 + h;
    bool valid = d < n;
    int dd = valid ? d : 0;
    unsigned m16 = h ? 0xFFFF0000u : 0x0000FFFFu;
    int j = l16 * 4;

    float4 xr4 = *(const float4*)&g_xr[(size_t)dd * DD + j];
    float4 at4 = *(const float4*)(att + j);
    float4 a6 = make_float4(0.6f * at4.x, 0.6f * at4.y, 0.6f * at4.z, 0.6f * at4.w);
    float4 a4 = make_float4(0.4f * at4.x, 0.4f * at4.y, 0.4f * at4.z, 0.4f * at4.w);

    float acc0 = 0.f, acc1 = 0.f, acc2 = 0.f, acc3 = 0.f, den = 0.f;

    // ---- self loop ----
    {
        uint2 raw = *(const uint2*)&g_xlh[(size_t)dd * DD + j];
        float2 a01 = __half22float2(*(__half2*)&raw.x);
        float2 a23 = __half22float2(*(__half2*)&raw.y);
        float m0 = a01.x + xr4.x, m1 = a01.y + xr4.y;
        float m2 = a23.x + xr4.z, m3 = a23.y + xr4.w;
        float part = m0 * a6.x;
        part = fmaf(fabsf(m0), a4.x, part);
        part = fmaf(m1, a6.y, part);
        part = fmaf(fabsf(m1), a4.y, part);
        part = fmaf(m2, a6.z, part);
        part = fmaf(fabsf(m2), a4.z, part);
        part = fmaf(m3, a6.w, part);
        part = fmaf(fabsf(m3), a4.w, part);
        part += __shfl_xor_sync(m16, part, 1, 16);
        part += __shfl_xor_sync(m16, part, 2, 16);
        float p = __expf(part);
        acc0 = p * a01.x; acc1 = p * a01.y;
        acc2 = p * a23.x; acc3 = p * a23.y;
        den = p;
    }

    int begin = valid ? g_rowptr[d] : 0;
    int end = valid ? g_rowptr[d + 1] : 0;

    for (int base = begin; base < end; base += 16) {
        int idx = base + l16;
        int sv = (idx < end) ? g_ssrc[idx] : dd;  // pad with self row (flag=0)
        int rem = end - base;

        // batched gather: 16 independent LDG.64
        uint2 raw[16];
#pragma unroll
        for (int k = 0; k < 16; k++) {
            int s = __shfl_sync(m16, sv, k, 16);
            raw[k] = *(const uint2*)&g_xlh[(size_t)s * DD + j];
        }

#pragma unroll
        for (int k = 0; k < 16; k++) {
            float2 a01 = __half22float2(*(__half2*)&raw[k].x);
            float2 a23 = __half22float2(*(__half2*)&raw[k].y);
            float m0 = a01.x + xr4.x, m1 = a01.y + xr4.y;
            float m2 = a23.x + xr4.z, m3 = a23.y + xr4.w;
            float part = m0 * a6.x;
            part = fmaf(fabsf(m0), a4.x, part);
            part = fmaf(m1, a6.y, part);
            part = fmaf(fabsf(m1), a4.y, part);
            part = fmaf(m2, a6.z, part);
            part = fmaf(fabsf(m2), a4.z, part);
            part = fmaf(m3, a6.w, part);
            part = fmaf(fabsf(m3), a4.w, part);
            part += __shfl_xor_sync(m16, part, 1, 16);
            part += __shfl_xor_sync(m16, part, 2, 16);
            float flag = (k < rem) ? 1.f : 0.f;
            float p = __expf(part) * flag;
            acc0 = fmaf(p, a01.x, acc0);
            acc1 = fmaf(p, a01.y, acc1);
            acc2 = fmaf(p, a23.x, acc2);
            acc3 = fmaf(p, a23.y, acc3);
            den += p;
        }
    }

    if (!valid) return;

    // ---- normalize + bias + residual ----
    float inv = 1.f / den;
    float4 xv = *(const float4*)&xres[(size_t)d * DD + j];
    float4 bi = *(const float4*)(bias + j);
    float v0 = acc0 * inv + bi.x + xv.x;
    float v1 = acc1 * inv + bi.y + xv.y;
    float v2 = acc2 * inv + bi.z + xv.z;
    float v3 = acc3 * inv + bi.w + xv.w;

    // ---- LayerNorm over 64 ch (16-lane reduce) ----
    float s = v0 + v1 + v2 + v3;
    float s2 = v0 * v0 + v1 * v1 + v2 * v2 + v3 * v3;
#pragma unroll
    for (int o = 8; o; o >>= 1) {
        s += __shfl_xor_sync(m16, s, o, 16);
        s2 += __shfl_xor_sync(m16, s2, o, 16);
    }
    float mu = s * (1.f / 64.f);
    float var = s2 * (1.f / 64.f) - mu * mu;
    float rstd = rsqrtf(var + 1e-5f);

    float4 ga = *(const float4*)(gamma + j);
    float4 be = *(const float4*)(beta + j);
    float y0 = (v0 - mu) * rstd * ga.x + be.x;
    float y1 = (v1 - mu) * rstd * ga.y + be.y;
    float y2 = (v2 - mu) * rstd * ga.z + be.z;
    float y3 = (v3 - mu) * rstd * ga.w + be.w;

    const float ks = 0.70710678118654752f;
    y0 = 0.5f * y0 * (1.f + erff(y0 * ks));
    y1 = 0.5f * y1 * (1.f + erff(y1 * ks));
    y2 = 0.5f * y2 * (1.f + erff(y2 * ks));
    y3 = 0.5f * y3 * (1.f + erff(y3 * ks));

    *(float4*)&out[(size_t)d * DD + j] = make_float4(y0, y1, y2, y3);
}

// ---------------------------------------------------------------------------
extern "C" void kernel_launch(void* const* d_in, const int* in_sizes, int n_in,
                              void* d_out, int out_size) {
    const float* x = (const float*)d_in[0];
    const int* ei = (const int*)d_in[1];   // int32: [src(E), dst(E)]
    const float* Wl = (const float*)d_in[2];
    const float* Wr = (const float*)d_in[3];
    const float* att = (const float*)d_in[4];
    const float* bias = (const float*)d_in[5];
    const float* gamma = (const float*)d_in[6];
    const float* beta = (const float*)d_in[7];

    int n = in_sizes[0] / DD;
    int E = in_sizes[1] / 2;
    int Lnum = in_sizes[2] / (DD * DD);

    float *b0p = nullptr, *b1p = nullptr;
    cudaGetSymbolAddress((void**)&b0p, g_b0);
    cudaGetSymbolAddress((void**)&b1p, g_b1);

    int nbScan = (n + SCAN_TILE - 1) / SCAN_TILE;
    const float* cur = x;
    int aggBlocks = (n + 15) / 16;  // 16 nodes per 256-thread block

    for (int i = 0; i < Lnum; i++) {
        // gemm first so that (layer 0) launch order is:
        // gemm(0) hist(1) scan1(2) scan23(3) scatter(4) agg(5)
        k_gemm<<<(n + 63) / 64, 256>>>(cur, Wl + (size_t)i * DD * DD,
                                       Wr + (size_t)i * DD * DD, n);
        if (i == 0) {
            k_hist<<<(E + 255) / 256, 256>>>(ei, E);
            k_scan1<<<nbScan, SCAN_BLK>>>(n);
            k_scan23<<<(n + 1 + 255) / 256, 256>>>(n, E, nbScan);
            k_scatter<<<(E + 255) / 256, 256>>>(ei, E);
        }

        float* outp;
        if (i == Lnum - 1) outp = (float*)d_out;
        else outp = (i & 1) ? b1p : b0p;

        k_agg<<<aggBlocks, 256>>>(cur, att + (size_t)i * DD,
                                  bias + (size_t)i * DD,
                                  gamma + (size_t)i * DD,
                                  beta + (size_t)i * DD,
                                  outp, n);
        cur = outp;
    }
}

// round 8
// speedup vs baseline: 1.1084x; 1.1084x over previous
#include <cuda_runtime.h>
#include <cuda_fp16.h>
#include <math.h>

// GATv2 (L=3, H=4, C=16, D=64), N=100000, E=1280000 (+N self loops).
// R8:
//  - agg = R4 shape (best known: warp = 2 nodes x 16 lanes, 4 ch/lane, unroll 4)
//  - CSR compressed to 2 extra launches: hist fused into layer-0 gemm,
//    scan1 publishes cross-tile prefix via atomicAdds into g_pre[32],
//    scatter/agg add g_pre[tile] on the fly.
//  - launch order: gemm+hist(0), scan1(1), scatter(2), agg(3) <- ncu captures #3
//  - max-L1 carveout on k_agg.

#define NNODES 100000
#define NEDGES 1280000
#define DD 64
#define SCAN_BLK 512
#define SCAN_ELEM 8
#define SCAN_TILE (SCAN_BLK * SCAN_ELEM)  // 4096

__device__ __align__(128) __half g_xlh[NNODES * DD];
__device__ __align__(16) float g_xr[NNODES * DD];
__device__ __align__(16) float g_b0[NNODES * DD];
__device__ __align__(16) float g_b1[NNODES * DD];
__device__ int g_cnt[NNODES];      // zero at load; scan1 re-zeroes after reading
__device__ int g_ofs[NNODES];      // tile-local running offsets (scatter bumps)
__device__ int g_rowptr[NNODES + 1];  // tile-local prefix; add g_pre[tile]
__device__ int g_pre[32];          // cross-tile exclusive prefix (zeroed by gemm L0)
__device__ int g_ssrc[NEDGES];

// ---------------------------------------------------------------------------
// GEMM: xl = x @ Wl (-> fp16), xr = x @ Wr (-> fp32).  K = 64.
// Layer 0 also: zero g_pre, histogram dst into g_cnt (grid-stride).
// ---------------------------------------------------------------------------
__global__ __launch_bounds__(256) void k_gemm(const float* __restrict__ x,
                                              const float* __restrict__ Wl,
                                              const float* __restrict__ Wr,
                                              int n,
                                              const int* __restrict__ ei,
                                              int E, int do_csr) {
    __shared__ float sWl[64][64];
    __shared__ float sWr[64][64];
    __shared__ float sxT[64][64];

    if (do_csr) {
        if (blockIdx.x == 0 && threadIdx.x < 32) g_pre[threadIdx.x] = 0;
        int stride = gridDim.x * blockDim.x;
        for (int e = blockIdx.x * blockDim.x + threadIdx.x; e < E; e += stride)
            atomicAdd(&g_cnt[ei[E + e]], 1);
    }

    int nodeBase = blockIdx.x * 64;

    for (int i = threadIdx.x; i < 64 * 64; i += 256) {
        sWl[i >> 6][i & 63] = Wl[i];
        sWr[i >> 6][i & 63] = Wr[i];
        int r = i >> 6, c = i & 63;
        int node = nodeBase + r;
        float v = (node < n) ? x[(size_t)node * DD + c] : 0.f;
        sxT[c][r] = v;
    }
    __syncthreads();

    int local = threadIdx.x >> 2;
    int cg = (threadIdx.x & 3) << 4;

    float accL[16], accR[16];
#pragma unroll
    for (int c = 0; c < 16; c++) { accL[c] = 0.f; accR[c] = 0.f; }

#pragma unroll 4
    for (int k = 0; k < 64; k++) {
        float xv = sxT[k][local];
        const float4* wl = (const float4*)&sWl[k][cg];
        const float4* wr = (const float4*)&sWr[k][cg];
#pragma unroll
        for (int q = 0; q < 4; q++) {
            float4 a = wl[q];
            float4 b = wr[q];
            accL[q * 4 + 0] = fmaf(xv, a.x, accL[q * 4 + 0]);
            accL[q * 4 + 1] = fmaf(xv, a.y, accL[q * 4 + 1]);
            accL[q * 4 + 2] = fmaf(xv, a.z, accL[q * 4 + 2]);
            accL[q * 4 + 3] = fmaf(xv, a.w, accL[q * 4 + 3]);
            accR[q * 4 + 0] = fmaf(xv, b.x, accR[q * 4 + 0]);
            accR[q * 4 + 1] = fmaf(xv, b.y, accR[q * 4 + 1]);
            accR[q * 4 + 2] = fmaf(xv, b.z, accR[q * 4 + 2]);
            accR[q * 4 + 3] = fmaf(xv, b.w, accR[q * 4 + 3]);
        }
    }

    int node = nodeBase + local;
    if (node < n) {
        __half2 hh[8];
#pragma unroll
        for (int q = 0; q < 8; q++)
            hh[q] = __floats2half2_rn(accL[2 * q], accL[2 * q + 1]);
        *(uint4*)&g_xlh[(size_t)node * DD + cg] = *(uint4*)&hh[0];
        *(uint4*)&g_xlh[(size_t)node * DD + cg + 8] = *(uint4*)&hh[4];

        float4* outr = (float4*)&g_xr[(size_t)node * DD + cg];
#pragma unroll
        for (int q = 0; q < 4; q++)
            outr[q] = make_float4(accR[q * 4 + 0], accR[q * 4 + 1], accR[q * 4 + 2], accR[q * 4 + 3]);
    }
}

// ---------------------------------------------------------------------------
// scan1: per-tile (4096) exclusive prefix of g_cnt -> g_rowptr/g_ofs (tile-
// local), zero g_cnt, publish tile totals to later tiles via atomicAdd g_pre.
// ---------------------------------------------------------------------------
__global__ __launch_bounds__(SCAN_BLK) void k_scan1(int n) {
    __shared__ int sh[SCAN_BLK];
    int blk = blockIdx.x;
    int base = blk * SCAN_TILE + threadIdx.x * SCAN_ELEM;
    int t = threadIdx.x;
    int v[SCAN_ELEM];
    int sum = 0;
#pragma unroll
    for (int i = 0; i < SCAN_ELEM; i++) {
        int idx = base + i;
        v[i] = (idx < n) ? g_cnt[idx] : 0;
        if (idx < n) g_cnt[idx] = 0;
        sum += v[i];
    }
    sh[t] = sum;
    __syncthreads();
    for (int o = 1; o < SCAN_BLK; o <<= 1) {
        int x = (t >= o) ? sh[t - o] : 0;
        __syncthreads();
        sh[t] += x;
        __syncthreads();
    }
    int run = (t > 0) ? sh[t - 1] : 0;
    if (t == SCAN_BLK - 1) {
        int total = sh[SCAN_BLK - 1];
        for (int j = blk + 1; j < gridDim.x; j++) atomicAdd(&g_pre[j], total);
    }
#pragma unroll
    for (int i = 0; i < SCAN_ELEM; i++) {
        int idx = base + i;
        if (idx < n) { g_rowptr[idx] = run; g_ofs[idx] = run; }
        if (idx == n - 1) g_rowptr[n] = run + v[i];
        run += v[i];
    }
}

__global__ void k_scatter(const int* __restrict__ ei, int E) {
    int e = blockIdx.x * blockDim.x + threadIdx.x;
    if (e < E) {
        int d = ei[E + e];
        int pos = atomicAdd(&g_ofs[d], 1) + __ldg(&g_pre[d >> 12]);
        g_ssrc[pos] = ei[e];
    }
}

// ---------------------------------------------------------------------------
// Fused aggregation (R4 shape): half-warp (16 lanes) per dst node, 4 ch/lane.
// ---------------------------------------------------------------------------
__device__ __forceinline__ void edge_accum(int s, int j, unsigned mask16,
                                           const float4& xr4,
                                           const float4& a6, const float4& a4,
                                           float& acc0, float& acc1,
                                           float& acc2, float& acc3,
                                           float& den) {
    uint2 raw = *(const uint2*)&g_xlh[(size_t)s * DD + j];
    float2 a01 = __half22float2(*(__half2*)&raw.x);
    float2 a23 = __half22float2(*(__half2*)&raw.y);

    float m0 = a01.x + xr4.x;
    float m1 = a01.y + xr4.y;
    float m2 = a23.x + xr4.z;
    float m3 = a23.y + xr4.w;

    float part = m0 * a6.x;
    part = fmaf(fabsf(m0), a4.x, part);
    part = fmaf(m1, a6.y, part);
    part = fmaf(fabsf(m1), a4.y, part);
    part = fmaf(m2, a6.z, part);
    part = fmaf(fabsf(m2), a4.z, part);
    part = fmaf(m3, a6.w, part);
    part = fmaf(fabsf(m3), a4.w, part);

    part += __shfl_xor_sync(mask16, part, 1, 16);
    part += __shfl_xor_sync(mask16, part, 2, 16);

    float p = __expf(part);
    acc0 = fmaf(p, a01.x, acc0);
    acc1 = fmaf(p, a01.y, acc1);
    acc2 = fmaf(p, a23.x, acc2);
    acc3 = fmaf(p, a23.y, acc3);
    den += p;
}

__global__ __launch_bounds__(256) void k_agg(const float* __restrict__ xres,
                                             const float* __restrict__ att,
                                             const float* __restrict__ bias,
                                             const float* __restrict__ gamma,
                                             const float* __restrict__ beta,
                                             float* __restrict__ out, int n) {
    int warp = (blockIdx.x * blockDim.x + threadIdx.x) >> 5;
    int lane = threadIdx.x & 31;
    int hf = lane >> 4;
    int l16 = lane & 15;
    int d = warp * 2 + hf;
    if (d >= n) return;
    unsigned mask16 = hf ? 0xFFFF0000u : 0x0000FFFFu;
    int j = l16 * 4;

    float4 xr4 = *(const float4*)&g_xr[(size_t)d * DD + j];
    float4 at4 = *(const float4*)(att + j);
    float4 a6 = make_float4(0.6f * at4.x, 0.6f * at4.y, 0.6f * at4.z, 0.6f * at4.w);
    float4 a4 = make_float4(0.4f * at4.x, 0.4f * at4.y, 0.4f * at4.z, 0.4f * at4.w);

    float acc0 = 0.f, acc1 = 0.f, acc2 = 0.f, acc3 = 0.f, den = 0.f;

    // self loop
    edge_accum(d, j, mask16, xr4, a6, a4, acc0, acc1, acc2, acc3, den);

    int pre0 = __ldg(&g_pre[d >> 12]);
    int pre1 = __ldg(&g_pre[(d + 1) >> 12]);
    int begin = g_rowptr[d] + pre0;
    int end = g_rowptr[d + 1] + pre1;

    for (int base = begin; base < end; base += 16) {
        int idx = base + l16;
        int sv = (idx < end) ? g_ssrc[idx] : 0;
        int cnt = end - base;
        if (cnt > 16) cnt = 16;
#pragma unroll 4
        for (int k = 0; k < cnt; k++) {
            int s = __shfl_sync(mask16, sv, k, 16);
            edge_accum(s, j, mask16, xr4, a6, a4, acc0, acc1, acc2, acc3, den);
        }
    }

    // normalize + bias + residual
    float inv = 1.f / den;
    float4 xv = *(const float4*)&xres[(size_t)d * DD + j];
    float4 bi = *(const float4*)(bias + j);
    float v0 = acc0 * inv + bi.x + xv.x;
    float v1 = acc1 * inv + bi.y + xv.y;
    float v2 = acc2 * inv + bi.z + xv.z;
    float v3 = acc3 * inv + bi.w + xv.w;

    // LayerNorm over 64 ch (16-lane reduce)
    float s = v0 + v1 + v2 + v3;
    float s2 = v0 * v0 + v1 * v1 + v2 * v2 + v3 * v3;
#pragma unroll
    for (int o = 8; o; o >>= 1) {
        s += __shfl_xor_sync(mask16, s, o, 16);
        s2 += __shfl_xor_sync(mask16, s2, o, 16);
    }
    float mu = s * (1.f / 64.f);
    float var = s2 * (1.f / 64.f) - mu * mu;
    float rstd = rsqrtf(var + 1e-5f);

    float4 ga = *(const float4*)(gamma + j);
    float4 be = *(const float4*)(beta + j);
    float y0 = (v0 - mu) * rstd * ga.x + be.x;
    float y1 = (v1 - mu) * rstd * ga.y + be.y;
    float y2 = (v2 - mu) * rstd * ga.z + be.z;
    float y3 = (v3 - mu) * rstd * ga.w + be.w;

    const float ks = 0.70710678118654752f;
    y0 = 0.5f * y0 * (1.f + erff(y0 * ks));
    y1 = 0.5f * y1 * (1.f + erff(y1 * ks));
    y2 = 0.5f * y2 * (1.f + erff(y2 * ks));
    y3 = 0.5f * y3 * (1.f + erff(y3 * ks));

    *(float4*)&out[(size_t)d * DD + j] = make_float4(y0, y1, y2, y3);
}

// ---------------------------------------------------------------------------
extern "C" void kernel_launch(void* const* d_in, const int* in_sizes, int n_in,
                              void* d_out, int out_size) {
    const float* x = (const float*)d_in[0];
    const int* ei = (const int*)d_in[1];   // int32: [src(E), dst(E)]
    const float* Wl = (const float*)d_in[2];
    const float* Wr = (const float*)d_in[3];
    const float* att = (const float*)d_in[4];
    const float* bias = (const float*)d_in[5];
    const float* gamma = (const float*)d_in[6];
    const float* beta = (const float*)d_in[7];

    int n = in_sizes[0] / DD;
    int E = in_sizes[1] / 2;
    int Lnum = in_sizes[2] / (DD * DD);

    float *b0p = nullptr, *b1p = nullptr;
    cudaGetSymbolAddress((void**)&b0p, g_b0);
    cudaGetSymbolAddress((void**)&b1p, g_b1);

    // maximize L1 for the gather kernel (no smem use)
    static int carveout_set = 0;
    if (!carveout_set) {
        cudaFuncSetAttribute(k_agg, cudaFuncAttributePreferredSharedMemoryCarveout, 0);
        cudaFuncSetAttribute(k_scatter, cudaFuncAttributePreferredSharedMemoryCarveout, 0);
        carveout_set = 1;
    }

    int nbScan = (n + SCAN_TILE - 1) / SCAN_TILE;
    const float* cur = x;
    int aggBlocks = (n + 15) / 16;  // 16 nodes per 256-thread block

    for (int i = 0; i < Lnum; i++) {
        // layer 0 launch order: gemm+hist(0), scan1(1), scatter(2), agg(3)
        k_gemm<<<(n + 63) / 64, 256>>>(cur, Wl + (size_t)i * DD * DD,
                                       Wr + (size_t)i * DD * DD, n,
                                       ei, E, i == 0 ? 1 : 0);
        if (i == 0) {
            k_scan1<<<nbScan, SCAN_BLK>>>(n);
            k_scatter<<<(E + 255) / 256, 256>>>(ei, E);
        }

        float* outp;
        if (i == Lnum - 1) outp = (float*)d_out;
        else outp = (i & 1) ? b1p : b0p;

        k_agg<<<aggBlocks, 256>>>(cur, att + (size_t)i * DD,
                                  bias + (size_t)i * DD,
                                  gamma + (size_t)i * DD,
                                  beta + (size_t)i * DD,
                                  outp, n);
        cur = outp;
    }
}

// round 9
// speedup vs baseline: 2.4317x; 2.1939x over previous
#include <cuda_runtime.h>
#include <cuda_fp16.h>
#include <math.h>

// GATv2 (L=3, H=4, C=16, D=64), N=100000, E=1280000 (+N self loops).
// R9:
//  - NEW register-tiled GEMM: block = 128 nodes x 128 outputs (Wl|Wr),
//    256 threads, 8x8 acc/thread, 4 LDS.128 per 64 FMA. Dynamic smem 66KB.
//  - agg unchanged (R4/R8 shape, 78.7us/layer measured).
//  - launch order: hist(0) scan1(1) scatter(2) gemm(3) agg(4) ... so ncu
//    (captures launch idx 3) profiles the new GEMM.

#define NNODES 100000
#define NEDGES 1280000
#define DD 64
#define GT 132                    // padded smem row stride (floats), 16B-aligned
#define SCAN_BLK 512
#define SCAN_ELEM 8
#define SCAN_TILE (SCAN_BLK * SCAN_ELEM)  // 4096

__device__ __align__(128) __half g_xlh[NNODES * DD];
__device__ __align__(16) float g_xr[NNODES * DD];
__device__ __align__(16) float g_b0[NNODES * DD];
__device__ __align__(16) float g_b1[NNODES * DD];
__device__ int g_cnt[NNODES];      // zero at load; scan1 re-zeroes after reading
__device__ int g_ofs[NNODES];
__device__ int g_rowptr[NNODES + 1];
__device__ int g_pre[32];          // zeroed by k_hist each replay
__device__ int g_ssrc[NEDGES];

// ------------------------- CSR build (once per launch) ----------------------
__global__ void k_hist(const int* __restrict__ ei, int E) {
    int e = blockIdx.x * blockDim.x + threadIdx.x;
    if (blockIdx.x == 0 && threadIdx.x < 32) g_pre[threadIdx.x] = 0;
    if (e < E) atomicAdd(&g_cnt[ei[E + e]], 1);
}

__global__ __launch_bounds__(SCAN_BLK) void k_scan1(int n) {
    __shared__ int sh[SCAN_BLK];
    int blk = blockIdx.x;
    int base = blk * SCAN_TILE + threadIdx.x * SCAN_ELEM;
    int t = threadIdx.x;
    int v[SCAN_ELEM];
    int sum = 0;
#pragma unroll
    for (int i = 0; i < SCAN_ELEM; i++) {
        int idx = base + i;
        v[i] = (idx < n) ? g_cnt[idx] : 0;
        if (idx < n) g_cnt[idx] = 0;
        sum += v[i];
    }
    sh[t] = sum;
    __syncthreads();
    for (int o = 1; o < SCAN_BLK; o <<= 1) {
        int x = (t >= o) ? sh[t - o] : 0;
        __syncthreads();
        sh[t] += x;
        __syncthreads();
    }
    int run = (t > 0) ? sh[t - 1] : 0;
    if (t == SCAN_BLK - 1) {
        int total = sh[SCAN_BLK - 1];
        for (int j = blk + 1; j < gridDim.x; j++) atomicAdd(&g_pre[j], total);
    }
#pragma unroll
    for (int i = 0; i < SCAN_ELEM; i++) {
        int idx = base + i;
        if (idx < n) { g_rowptr[idx] = run; g_ofs[idx] = run; }
        if (idx == n - 1) g_rowptr[n] = run + v[i];
        run += v[i];
    }
}

__global__ void k_scatter(const int* __restrict__ ei, int E) {
    int e = blockIdx.x * blockDim.x + threadIdx.x;
    if (e < E) {
        int d = ei[E + e];
        int pos = atomicAdd(&g_ofs[d], 1) + __ldg(&g_pre[d >> 12]);
        g_ssrc[pos] = ei[e];
    }
}

// ---------------------------------------------------------------------------
// Register-tiled GEMM: [128 nodes] x [128 outputs] per block, 256 threads,
// 8x8 accumulators per thread.  outputs 0..63 = x@Wl (-> fp16 g_xlh),
// outputs 64..127 = x@Wr (-> fp32 g_xr).
// ---------------------------------------------------------------------------
__global__ __launch_bounds__(256) void k_gemm(const float* __restrict__ x,
                                              const float* __restrict__ Wl,
                                              const float* __restrict__ Wr,
                                              int n) {
    extern __shared__ float sm[];
    float* sxT = sm;            // [64][GT]  x transposed: [k][node]
    float* sW  = sm + 64 * GT;  // [64][GT]  weights: [k][col], col 0..63 Wl, 64..127 Wr

    int tid = threadIdx.x;
    int nodeBase = blockIdx.x * 128;

    // weights: 2 x (64x64) = 1024 float4 reads each
    for (int g = tid; g < 1024; g += 256) {
        int k = g >> 4;
        int cq = (g & 15) << 2;
        float4 wl = *(const float4*)&Wl[k * 64 + cq];
        float4 wr = *(const float4*)&Wr[k * 64 + cq];
        *(float4*)&sW[k * GT + cq] = wl;
        *(float4*)&sW[k * GT + 64 + cq] = wr;
    }

    // x tile: 128 nodes x 64 ch, transposed into sxT[k][node]
    for (int g = tid; g < 2048; g += 256) {
        int node = g >> 4;
        int kq = (g & 15) << 2;
        int gn = nodeBase + node;
        float4 v = (gn < n) ? *(const float4*)&x[(size_t)gn * DD + kq]
                            : make_float4(0.f, 0.f, 0.f, 0.f);
        sxT[(kq + 0) * GT + node] = v.x;
        sxT[(kq + 1) * GT + node] = v.y;
        sxT[(kq + 2) * GT + node] = v.z;
        sxT[(kq + 3) * GT + node] = v.w;
    }
    __syncthreads();

    int tx = tid & 15, ty = tid >> 4;
    int col8 = tx * 8;    // output columns col8..col8+7
    int node8 = ty * 8;   // nodes node8..node8+7

    float acc[8][8];
#pragma unroll
    for (int i = 0; i < 8; i++)
#pragma unroll
        for (int jj = 0; jj < 8; jj++) acc[i][jj] = 0.f;

#pragma unroll 2
    for (int k = 0; k < 64; k++) {
        float4 xa = *(const float4*)&sxT[k * GT + node8];
        float4 xb = *(const float4*)&sxT[k * GT + node8 + 4];
        float4 wa = *(const float4*)&sW[k * GT + col8];
        float4 wb = *(const float4*)&sW[k * GT + col8 + 4];
        float xv[8] = {xa.x, xa.y, xa.z, xa.w, xb.x, xb.y, xb.z, xb.w};
        float wv[8] = {wa.x, wa.y, wa.z, wa.w, wb.x, wb.y, wb.z, wb.w};
#pragma unroll
        for (int i = 0; i < 8; i++)
#pragma unroll
            for (int jj = 0; jj < 8; jj++)
                acc[i][jj] = fmaf(xv[i], wv[jj], acc[i][jj]);
    }

    bool isL = col8 < 64;
    int colr = isL ? col8 : (col8 - 64);
#pragma unroll
    for (int i = 0; i < 8; i++) {
        int gn = nodeBase + node8 + i;
        if (gn < n) {
            if (isL) {
                __half2 h[4];
#pragma unroll
                for (int q = 0; q < 4; q++)
                    h[q] = __floats2half2_rn(acc[i][2 * q], acc[i][2 * q + 1]);
                *(uint4*)&g_xlh[(size_t)gn * DD + colr] = *(uint4*)h;
            } else {
                *(float4*)&g_xr[(size_t)gn * DD + colr] =
                    make_float4(acc[i][0], acc[i][1], acc[i][2], acc[i][3]);
                *(float4*)&g_xr[(size_t)gn * DD + colr + 4] =
                    make_float4(acc[i][4], acc[i][5], acc[i][6], acc[i][7]);
            }
        }
    }
}

// ---------------------------------------------------------------------------
// Fused aggregation (unchanged): half-warp per dst node, 4 ch/lane.
// ---------------------------------------------------------------------------
__device__ __forceinline__ void edge_accum(int s, int j, unsigned mask16,
                                           const float4& xr4,
                                           const float4& a6, const float4& a4,
                                           float& acc0, float& acc1,
                                           float& acc2, float& acc3,
                                           float& den) {
    uint2 raw = *(const uint2*)&g_xlh[(size_t)s * DD + j];
    float2 a01 = __half22float2(*(__half2*)&raw.x);
    float2 a23 = __half22float2(*(__half2*)&raw.y);

    float m0 = a01.x + xr4.x;
    float m1 = a01.y + xr4.y;
    float m2 = a23.x + xr4.z;
    float m3 = a23.y + xr4.w;

    float part = m0 * a6.x;
    part = fmaf(fabsf(m0), a4.x, part);
    part = fmaf(m1, a6.y, part);
    part = fmaf(fabsf(m1), a4.y, part);
    part = fmaf(m2, a6.z, part);
    part = fmaf(fabsf(m2), a4.z, part);
    part = fmaf(m3, a6.w, part);
    part = fmaf(fabsf(m3), a4.w, part);

    part += __shfl_xor_sync(mask16, part, 1, 16);
    part += __shfl_xor_sync(mask16, part, 2, 16);

    float p = __expf(part);
    acc0 = fmaf(p, a01.x, acc0);
    acc1 = fmaf(p, a01.y, acc1);
    acc2 = fmaf(p, a23.x, acc2);
    acc3 = fmaf(p, a23.y, acc3);
    den += p;
}

__global__ __launch_bounds__(256) void k_agg(const float* __restrict__ xres,
                                             const float* __restrict__ att,
                                             const float* __restrict__ bias,
                                             const float* __restrict__ gamma,
                                             const float* __restrict__ beta,
                                             float* __restrict__ out, int n) {
    int warp = (blockIdx.x * blockDim.x + threadIdx.x) >> 5;
    int lane = threadIdx.x & 31;
    int hf = lane >> 4;
    int l16 = lane & 15;
    int d = warp * 2 + hf;
    if (d >= n) return;
    unsigned mask16 = hf ? 0xFFFF0000u : 0x0000FFFFu;
    int j = l16 * 4;

    float4 xr4 = *(const float4*)&g_xr[(size_t)d * DD + j];
    float4 at4 = *(const float4*)(att + j);
    float4 a6 = make_float4(0.6f * at4.x, 0.6f * at4.y, 0.6f * at4.z, 0.6f * at4.w);
    float4 a4 = make_float4(0.4f * at4.x, 0.4f * at4.y, 0.4f * at4.z, 0.4f * at4.w);

    float acc0 = 0.f, acc1 = 0.f, acc2 = 0.f, acc3 = 0.f, den = 0.f;

    // self loop
    edge_accum(d, j, mask16, xr4, a6, a4, acc0, acc1, acc2, acc3, den);

    int pre0 = __ldg(&g_pre[d >> 12]);
    int pre1 = __ldg(&g_pre[(d + 1) >> 12]);
    int begin = g_rowptr[d] + pre0;
    int end = g_rowptr[d + 1] + pre1;

    for (int base = begin; base < end; base += 16) {
        int idx = base + l16;
        int sv = (idx < end) ? g_ssrc[idx] : 0;
        int cnt = end - base;
        if (cnt > 16) cnt = 16;
#pragma unroll 4
        for (int k = 0; k < cnt; k++) {
            int s = __shfl_sync(mask16, sv, k, 16);
            edge_accum(s, j, mask16, xr4, a6, a4, acc0, acc1, acc2, acc3, den);
        }
    }

    // normalize + bias + residual
    float inv = 1.f / den;
    float4 xv = *(const float4*)&xres[(size_t)d * DD + j];
    float4 bi = *(const float4*)(bias + j);
    float v0 = acc0 * inv + bi.x + xv.x;
    float v1 = acc1 * inv + bi.y + xv.y;
    float v2 = acc2 * inv + bi.z + xv.z;
    float v3 = acc3 * inv + bi.w + xv.w;

    // LayerNorm over 64 ch (16-lane reduce)
    float s = v0 + v1 + v2 + v3;
    float s2 = v0 * v0 + v1 * v1 + v2 * v2 + v3 * v3;
#pragma unroll
    for (int o = 8; o; o >>= 1) {
        s += __shfl_xor_sync(mask16, s, o, 16);
        s2 += __shfl_xor_sync(mask16, s2, o, 16);
    }
    float mu = s * (1.f / 64.f);
    float var = s2 * (1.f / 64.f) - mu * mu;
    float rstd = rsqrtf(var + 1e-5f);

    float4 ga = *(const float4*)(gamma + j);
    float4 be = *(const float4*)(beta + j);
    float y0 = (v0 - mu) * rstd * ga.x + be.x;
    float y1 = (v1 - mu) * rstd * ga.y + be.y;
    float y2 = (v2 - mu) * rstd * ga.z + be.z;
    float y3 = (v3 - mu) * rstd * ga.w + be.w;

    const float ks = 0.70710678118654752f;
    y0 = 0.5f * y0 * (1.f + erff(y0 * ks));
    y1 = 0.5f * y1 * (1.f + erff(y1 * ks));
    y2 = 0.5f * y2 * (1.f + erff(y2 * ks));
    y3 = 0.5f * y3 * (1.f + erff(y3 * ks));

    *(float4*)&out[(size_t)d * DD + j] = make_float4(y0, y1, y2, y3);
}

// ---------------------------------------------------------------------------
extern "C" void kernel_launch(void* const* d_in, const int* in_sizes, int n_in,
                              void* d_out, int out_size) {
    const float* x = (const float*)d_in[0];
    const int* ei = (const int*)d_in[1];   // int32: [src(E), dst(E)]
    const float* Wl = (const float*)d_in[2];
    const float* Wr = (const float*)d_in[3];
    const float* att = (const float*)d_in[4];
    const float* bias = (const float*)d_in[5];
    const float* gamma = (const float*)d_in[6];
    const float* beta = (const float*)d_in[7];

    int n = in_sizes[0] / DD;
    int E = in_sizes[1] / 2;
    int Lnum = in_sizes[2] / (DD * DD);

    float *b0p = nullptr, *b1p = nullptr;
    cudaGetSymbolAddress((void**)&b0p, g_b0);
    cudaGetSymbolAddress((void**)&b1p, g_b1);

    const int gemmSmem = 2 * 64 * GT * (int)sizeof(float);  // 67584 B

    static int attr_set = 0;
    if (!attr_set) {
        cudaFuncSetAttribute(k_gemm, cudaFuncAttributeMaxDynamicSharedMemorySize, gemmSmem);
        cudaFuncSetAttribute(k_agg, cudaFuncAttributePreferredSharedMemoryCarveout, 0);
        attr_set = 1;
    }

    int nbScan = (n + SCAN_TILE - 1) / SCAN_TILE;
    const float* cur = x;
    int aggBlocks = (n + 15) / 16;

    // launch order: hist(0) scan1(1) scatter(2) gemm(3) agg(4) gemm agg ...
    k_hist<<<(E + 255) / 256, 256>>>(ei, E);
    k_scan1<<<nbScan, SCAN_BLK>>>(n);
    k_scatter<<<(E + 255) / 256, 256>>>(ei, E);

    for (int i = 0; i < Lnum; i++) {
        k_gemm<<<(n + 127) / 128, 256, gemmSmem>>>(cur, Wl + (size_t)i * DD * DD,
                                                   Wr + (size_t)i * DD * DD, n);

        float* outp;
        if (i == Lnum - 1) outp = (float*)d_out;
        else outp = (i & 1) ? b1p : b0p;

        k_agg<<<aggBlocks, 256>>>(cur, att + (size_t)i * DD,
                                  bias + (size_t)i * DD,
                                  gamma + (size_t)i * DD,
                                  beta + (size_t)i * DD,
                                  outp, n);
        cur = outp;
    }
}

// round 10
// speedup vs baseline: 3.0074x; 1.2367x over previous
#include <cuda_runtime.h>
#include <cuda_fp16.h>
#include <mma.h>
#include <math.h>

using namespace nvcuda;

// GATv2 (L=3, H=4, C=16, D=64), N=100000, E=1280000 (+N self loops).
// R10:
//  - GEMM -> tensor cores (wmma fp16 x fp16 -> fp32): block = 128 nodes x 128
//    cols (Wl|Wr), 8 warps, each 64x32 via 4x2 16x16x16 fragments.
//    xr fragments stored directly to gmem (g_xr padded +128 rows);
//    xl staged via smem (aliased) for fp32->fp16 conversion.
//  - agg unchanged (R8 shape, measured 78.7us/layer).
//  - launch order: hist(0) scan1(1) scatter(2) gemm(3) agg(4) ...

#define NNODES 100000
#define NEDGES 1280000
#define DD 64
#define XH_LD 72     // halves per row, x tile
#define W_LD 136     // halves per row, W tile
#define ST_LD 72     // floats per row, xl staging
#define SCAN_BLK 512
#define SCAN_ELEM 8
#define SCAN_TILE (SCAN_BLK * SCAN_ELEM)  // 4096

__device__ __align__(128) __half g_xlh[NNODES * DD];
__device__ __align__(128) float g_xr[(NNODES + 128) * DD];  // +128 rows: wmma tile overhang
__device__ __align__(16) float g_b0[NNODES * DD];
__device__ __align__(16) float g_b1[NNODES * DD];
__device__ int g_cnt[NNODES];      // zero at load; scan1 re-zeroes after reading
__device__ int g_ofs[NNODES];
__device__ int g_rowptr[NNODES + 1];
__device__ int g_pre[32];          // zeroed by k_hist each replay
__device__ int g_ssrc[NEDGES];

// ------------------------- CSR build (once per launch) ----------------------
__global__ void k_hist(const int* __restrict__ ei, int E) {
    int e = blockIdx.x * blockDim.x + threadIdx.x;
    if (blockIdx.x == 0 && threadIdx.x < 32) g_pre[threadIdx.x] = 0;
    if (e < E) atomicAdd(&g_cnt[ei[E + e]], 1);
}

__global__ __launch_bounds__(SCAN_BLK) void k_scan1(int n) {
    __shared__ int sh[SCAN_BLK];
    int blk = blockIdx.x;
    int base = blk * SCAN_TILE + threadIdx.x * SCAN_ELEM;
    int t = threadIdx.x;
    int v[SCAN_ELEM];
    int sum = 0;
#pragma unroll
    for (int i = 0; i < SCAN_ELEM; i++) {
        int idx = base + i;
        v[i] = (idx < n) ? g_cnt[idx] : 0;
        if (idx < n) g_cnt[idx] = 0;
        sum += v[i];
    }
    sh[t] = sum;
    __syncthreads();
    for (int o = 1; o < SCAN_BLK; o <<= 1) {
        int x = (t >= o) ? sh[t - o] : 0;
        __syncthreads();
        sh[t] += x;
        __syncthreads();
    }
    int run = (t > 0) ? sh[t - 1] : 0;
    if (t == SCAN_BLK - 1) {
        int total = sh[SCAN_BLK - 1];
        for (int j = blk + 1; j < gridDim.x; j++) atomicAdd(&g_pre[j], total);
    }
#pragma unroll
    for (int i = 0; i < SCAN_ELEM; i++) {
        int idx = base + i;
        if (idx < n) { g_rowptr[idx] = run; g_ofs[idx] = run; }
        if (idx == n - 1) g_rowptr[n] = run + v[i];
        run += v[i];
    }
}

__global__ void k_scatter(const int* __restrict__ ei, int E) {
    int e = blockIdx.x * blockDim.x + threadIdx.x;
    if (e < E) {
        int d = ei[E + e];
        int pos = atomicAdd(&g_ofs[d], 1) + __ldg(&g_pre[d >> 12]);
        g_ssrc[pos] = ei[e];
    }
}

// ---------------------------------------------------------------------------
// Tensor-core GEMM: [128 nodes] x [128 cols] per block (cols 0..63 -> xl fp16,
// 64..127 -> xr fp32). 256 threads = 8 warps; warp (wr,wc) computes the
// 64x32 patch rows wr*64.., cols wc*32.. as 4x2 wmma 16x16x16 fragments.
// ---------------------------------------------------------------------------
__global__ __launch_bounds__(256) void k_gemm(const float* __restrict__ x,
                                              const float* __restrict__ Wl,
                                              const float* __restrict__ Wr,
                                              int n) {
    extern __shared__ char smraw[];
    __half* xh = (__half*)smraw;                          // [128][XH_LD]
    __half* wh = (__half*)(smraw + 128 * XH_LD * 2);      // [64][W_LD]
    float* stg = (float*)smraw;                           // [128][ST_LD] (aliased)

    int tid = threadIdx.x;
    int nodeBase = blockIdx.x * 128;

    // x tile -> fp16 smem (zero-pad past n)
    for (int g = tid; g < 2048; g += 256) {
        int row = g >> 4;
        int c4 = (g & 15) << 2;
        int gn = nodeBase + row;
        float4 v = (gn < n) ? *(const float4*)&x[(size_t)gn * DD + c4]
                            : make_float4(0.f, 0.f, 0.f, 0.f);
        __half2 h0 = __floats2half2_rn(v.x, v.y);
        __half2 h1 = __floats2half2_rn(v.z, v.w);
        uint2 pk;
        pk.x = *(unsigned*)&h0;
        pk.y = *(unsigned*)&h1;
        *(uint2*)&xh[row * XH_LD + c4] = pk;
    }
    // W -> fp16 smem: wh[k][col], col 0..63 Wl, 64..127 Wr
    for (int g = tid; g < 2048; g += 256) {
        int k = g >> 5;
        int c4 = (g & 31) << 2;
        float4 v = (c4 < 64) ? *(const float4*)&Wl[k * 64 + c4]
                             : *(const float4*)&Wr[k * 64 + (c4 - 64)];
        __half2 h0 = __floats2half2_rn(v.x, v.y);
        __half2 h1 = __floats2half2_rn(v.z, v.w);
        uint2 pk;
        pk.x = *(unsigned*)&h0;
        pk.y = *(unsigned*)&h1;
        *(uint2*)&wh[k * W_LD + c4] = pk;
    }
    __syncthreads();

    int warp = tid >> 5;
    int wr = warp >> 2;        // 0..1 : row block (64 rows)
    int wc = warp & 3;         // 0..3 : col block (32 cols)

    wmma::fragment<wmma::accumulator, 16, 16, 16, float> cf[4][2];
#pragma unroll
    for (int i = 0; i < 4; i++)
#pragma unroll
        for (int j = 0; j < 2; j++) wmma::fill_fragment(cf[i][j], 0.f);

#pragma unroll
    for (int kk = 0; kk < 64; kk += 16) {
        wmma::fragment<wmma::matrix_a, 16, 16, 16, __half, wmma::row_major> af[4];
        wmma::fragment<wmma::matrix_b, 16, 16, 16, __half, wmma::row_major> bf[2];
#pragma unroll
        for (int i = 0; i < 4; i++)
            wmma::load_matrix_sync(af[i], &xh[(wr * 64 + i * 16) * XH_LD + kk], XH_LD);
#pragma unroll
        for (int j = 0; j < 2; j++)
            wmma::load_matrix_sync(bf[j], &wh[kk * W_LD + wc * 32 + j * 16], W_LD);
#pragma unroll
        for (int i = 0; i < 4; i++)
#pragma unroll
            for (int j = 0; j < 2; j++)
                wmma::mma_sync(cf[i][j], af[i], bf[j], cf[i][j]);
    }

    __syncthreads();  // everyone done reading xh/wh before staging reuse

    if (wc >= 2) {
        // xr: direct global store (g_xr has +128 row padding for overhang)
        int colBase = wc * 32 - 64;
#pragma unroll
        for (int i = 0; i < 4; i++) {
            int gr = nodeBase + wr * 64 + i * 16;
#pragma unroll
            for (int j = 0; j < 2; j++)
                wmma::store_matrix_sync(&g_xr[(size_t)gr * DD + colBase + j * 16],
                                        cf[i][j], DD, wmma::mem_row_major);
        }
    } else {
        // xl: stage fp32 to smem for conversion
#pragma unroll
        for (int i = 0; i < 4; i++) {
            int r0 = wr * 64 + i * 16;
#pragma unroll
            for (int j = 0; j < 2; j++)
                wmma::store_matrix_sync(&stg[r0 * ST_LD + wc * 32 + j * 16],
                                        cf[i][j], ST_LD, wmma::mem_row_major);
        }
    }
    __syncthreads();

    // cooperative xl write: 128 rows x 64 cols fp32 -> fp16
    for (int g = tid; g < 2048; g += 256) {
        int row = g >> 4;
        int c4 = (g & 15) << 2;
        int gn = nodeBase + row;
        if (gn < n) {
            const float* p = &stg[row * ST_LD + c4];
            __half2 h0 = __floats2half2_rn(p[0], p[1]);
            __half2 h1 = __floats2half2_rn(p[2], p[3]);
            uint2 pk;
            pk.x = *(unsigned*)&h0;
            pk.y = *(unsigned*)&h1;
            *(uint2*)&g_xlh[(size_t)gn * DD + c4] = pk;
        }
    }
}

// ---------------------------------------------------------------------------
// Fused aggregation (unchanged): half-warp per dst node, 4 ch/lane.
// ---------------------------------------------------------------------------
__device__ __forceinline__ void edge_accum(int s, int j, unsigned mask16,
                                           const float4& xr4,
                                           const float4& a6, const float4& a4,
                                           float& acc0, float& acc1,
                                           float& acc2, float& acc3,
                                           float& den) {
    uint2 raw = *(const uint2*)&g_xlh[(size_t)s * DD + j];
    float2 a01 = __half22float2(*(__half2*)&raw.x);
    float2 a23 = __half22float2(*(__half2*)&raw.y);

    float m0 = a01.x + xr4.x;
    float m1 = a01.y + xr4.y;
    float m2 = a23.x + xr4.z;
    float m3 = a23.y + xr4.w;

    float part = m0 * a6.x;
    part = fmaf(fabsf(m0), a4.x, part);
    part = fmaf(m1, a6.y, part);
    part = fmaf(fabsf(m1), a4.y, part);
    part = fmaf(m2, a6.z, part);
    part = fmaf(fabsf(m2), a4.z, part);
    part = fmaf(m3, a6.w, part);
    part = fmaf(fabsf(m3), a4.w, part);

    part += __shfl_xor_sync(mask16, part, 1, 16);
    part += __shfl_xor_sync(mask16, part, 2, 16);

    float p = __expf(part);
    acc0 = fmaf(p, a01.x, acc0);
    acc1 = fmaf(p, a01.y, acc1);
    acc2 = fmaf(p, a23.x, acc2);
    acc3 = fmaf(p, a23.y, acc3);
    den += p;
}

__global__ __launch_bounds__(256) void k_agg(const float* __restrict__ xres,
                                             const float* __restrict__ att,
                                             const float* __restrict__ bias,
                                             const float* __restrict__ gamma,
                                             const float* __restrict__ beta,
                                             float* __restrict__ out, int n) {
    int warp = (blockIdx.x * blockDim.x + threadIdx.x) >> 5;
    int lane = threadIdx.x & 31;
    int hf = lane >> 4;
    int l16 = lane & 15;
    int d = warp * 2 + hf;
    if (d >= n) return;
    unsigned mask16 = hf ? 0xFFFF0000u : 0x0000FFFFu;
    int j = l16 * 4;

    float4 xr4 = *(const float4*)&g_xr[(size_t)d * DD + j];
    float4 at4 = *(const float4*)(att + j);
    float4 a6 = make_float4(0.6f * at4.x, 0.6f * at4.y, 0.6f * at4.z, 0.6f * at4.w);
    float4 a4 = make_float4(0.4f * at4.x, 0.4f * at4.y, 0.4f * at4.z, 0.4f * at4.w);

    float acc0 = 0.f, acc1 = 0.f, acc2 = 0.f, acc3 = 0.f, den = 0.f;

    // self loop
    edge_accum(d, j, mask16, xr4, a6, a4, acc0, acc1, acc2, acc3, den);

    int pre0 = __ldg(&g_pre[d >> 12]);
    int pre1 = __ldg(&g_pre[(d + 1) >> 12]);
    int begin = g_rowptr[d] + pre0;
    int end = g_rowptr[d + 1] + pre1;

    for (int base = begin; base < end; base += 16) {
        int idx = base + l16;
        int sv = (idx < end) ? g_ssrc[idx] : 0;
        int cnt = end - base;
        if (cnt > 16) cnt = 16;
#pragma unroll 4
        for (int k = 0; k < cnt; k++) {
            int s = __shfl_sync(mask16, sv, k, 16);
            edge_accum(s, j, mask16, xr4, a6, a4, acc0, acc1, acc2, acc3, den);
        }
    }

    // normalize + bias + residual
    float inv = 1.f / den;
    float4 xv = *(const float4*)&xres[(size_t)d * DD + j];
    float4 bi = *(const float4*)(bias + j);
    float v0 = acc0 * inv + bi.x + xv.x;
    float v1 = acc1 * inv + bi.y + xv.y;
    float v2 = acc2 * inv + bi.z + xv.z;
    float v3 = acc3 * inv + bi.w + xv.w;

    // LayerNorm over 64 ch (16-lane reduce)
    float s = v0 + v1 + v2 + v3;
    float s2 = v0 * v0 + v1 * v1 + v2 * v2 + v3 * v3;
#pragma unroll
    for (int o = 8; o; o >>= 1) {
        s += __shfl_xor_sync(mask16, s, o, 16);
        s2 += __shfl_xor_sync(mask16, s2, o, 16);
    }
    float mu = s * (1.f / 64.f);
    float var = s2 * (1.f / 64.f) - mu * mu;
    float rstd = rsqrtf(var + 1e-5f);

    float4 ga = *(const float4*)(gamma + j);
    float4 be = *(const float4*)(beta + j);
    float y0 = (v0 - mu) * rstd * ga.x + be.x;
    float y1 = (v1 - mu) * rstd * ga.y + be.y;
    float y2 = (v2 - mu) * rstd * ga.z + be.z;
    float y3 = (v3 - mu) * rstd * ga.w + be.w;

    const float ks = 0.70710678118654752f;
    y0 = 0.5f * y0 * (1.f + erff(y0 * ks));
    y1 = 0.5f * y1 * (1.f + erff(y1 * ks));
    y2 = 0.5f * y2 * (1.f + erff(y2 * ks));
    y3 = 0.5f * y3 * (1.f + erff(y3 * ks));

    *(float4*)&out[(size_t)d * DD + j] = make_float4(y0, y1, y2, y3);
}

// ---------------------------------------------------------------------------
extern "C" void kernel_launch(void* const* d_in, const int* in_sizes, int n_in,
                              void* d_out, int out_size) {
    const float* x = (const float*)d_in[0];
    const int* ei = (const int*)d_in[1];   // int32: [src(E), dst(E)]
    const float* Wl = (const float*)d_in[2];
    const float* Wr = (const float*)d_in[3];
    const float* att = (const float*)d_in[4];
    const float* bias = (const float*)d_in[5];
    const float* gamma = (const float*)d_in[6];
    const float* beta = (const float*)d_in[7];

    int n = in_sizes[0] / DD;
    int E = in_sizes[1] / 2;
    int Lnum = in_sizes[2] / (DD * DD);

    float *b0p = nullptr, *b1p = nullptr;
    cudaGetSymbolAddress((void**)&b0p, g_b0);
    cudaGetSymbolAddress((void**)&b1p, g_b1);

    const int inputBytes = 128 * XH_LD * 2 + 64 * W_LD * 2;   // 35840
    const int stageBytes = 128 * ST_LD * 4;                   // 36864
    const int gemmSmem = (stageBytes > inputBytes) ? stageBytes : inputBytes;

    static int attr_set = 0;
    if (!attr_set) {
        cudaFuncSetAttribute(k_gemm, cudaFuncAttributeMaxDynamicSharedMemorySize, gemmSmem);
        cudaFuncSetAttribute(k_agg, cudaFuncAttributePreferredSharedMemoryCarveout, 0);
        attr_set = 1;
    }

    int nbScan = (n + SCAN_TILE - 1) / SCAN_TILE;
    const float* cur = x;
    int aggBlocks = (n + 15) / 16;

    // launch order: hist(0) scan1(1) scatter(2) gemm(3) agg(4) ...
    k_hist<<<(E + 255) / 256, 256>>>(ei, E);
    k_scan1<<<nbScan, SCAN_BLK>>>(n);
    k_scatter<<<(E + 255) / 256, 256>>>(ei, E);

    for (int i = 0; i < Lnum; i++) {
        k_gemm<<<(n + 127) / 128, 256, gemmSmem>>>(cur, Wl + (size_t)i * DD * DD,
                                                   Wr + (size_t)i * DD * DD, n);

        float* outp;
        if (i == Lnum - 1) outp = (float*)d_out;
        else outp = (i & 1) ? b1p : b0p;

        k_agg<<<aggBlocks, 256>>>(cur, att + (size_t)i * DD,
                                  bias + (size_t)i * DD,
                                  gamma + (size_t)i * DD,
                                  beta + (size_t)i * DD,
                                  outp, n);
        cur = outp;
    }
}

// round 11
// speedup vs baseline: 3.1132x; 1.0352x over previous
#include <cuda_runtime.h>
#include <cuda_fp16.h>
#include <mma.h>
#include <math.h>

using namespace nvcuda;

// GATv2 (L=3, H=4, C=16, D=64), N=100000, E=1280000 (+N self loops).
// R11:
//  - GEMM: wmma fp16 -> xl accumulated in fp16 and stored DIRECTLY to g_xlh
//    (padded +128 rows); xr fp32 acc stored directly to g_xr (padded).
//    No staging buffer, 2 syncs, smem = input tiles only (35.8KB).
//    Layer-0 gemm also zeroes g_pre and histograms dst (grid-stride).
//  - agg byte-identical to R8/R10 (isolate variables).
//  - launch order: gemm+hist(0), scan1(1), scatter(2), agg(3) -> ncu idx3 = agg.

#define NNODES 100000
#define NEDGES 1280000
#define DD 64
#define XH_LD 72     // halves per row, x tile
#define W_LD 136     // halves per row, W tile
#define SCAN_BLK 512
#define SCAN_ELEM 8
#define SCAN_TILE (SCAN_BLK * SCAN_ELEM)  // 4096

__device__ __align__(128) __half g_xlh[(NNODES + 128) * DD];  // +128 rows: wmma overhang
__device__ __align__(128) float g_xr[(NNODES + 128) * DD];    // +128 rows: wmma overhang
__device__ __align__(16) float g_b0[NNODES * DD];
__device__ __align__(16) float g_b1[NNODES * DD];
__device__ int g_cnt[NNODES];      // zero at load; scan1 re-zeroes after reading
__device__ int g_ofs[NNODES];
__device__ int g_rowptr[NNODES + 1];
__device__ int g_pre[32];          // zeroed by layer-0 gemm each replay
__device__ int g_ssrc[NEDGES];

// ---------------------------------------------------------------------------
// Tensor-core GEMM: [128 nodes] x [128 cols] per block. 8 warps, each 64x32.
// cols 0..63 -> xl (fp16 acc, direct store), 64..127 -> xr (fp32 acc, direct).
// Layer 0 (do_csr): zero g_pre + histogram dst.
// ---------------------------------------------------------------------------
__global__ __launch_bounds__(256) void k_gemm(const float* __restrict__ x,
                                              const float* __restrict__ Wl,
                                              const float* __restrict__ Wr,
                                              int n,
                                              const int* __restrict__ ei,
                                              int E, int do_csr) {
    extern __shared__ char smraw[];
    __half* xh = (__half*)smraw;                          // [128][XH_LD]
    __half* wh = (__half*)(smraw + 128 * XH_LD * 2);      // [64][W_LD]

    int tid = threadIdx.x;
    int nodeBase = blockIdx.x * 128;

    if (do_csr) {
        if (blockIdx.x == 0 && tid < 32) g_pre[tid] = 0;
        int stride = gridDim.x * blockDim.x;
        for (int e = blockIdx.x * blockDim.x + tid; e < E; e += stride)
            atomicAdd(&g_cnt[ei[E + e]], 1);
    }

    // x tile -> fp16 smem (zero-pad past n)
    for (int g = tid; g < 2048; g += 256) {
        int row = g >> 4;
        int c4 = (g & 15) << 2;
        int gn = nodeBase + row;
        float4 v = (gn < n) ? *(const float4*)&x[(size_t)gn * DD + c4]
                            : make_float4(0.f, 0.f, 0.f, 0.f);
        __half2 h0 = __floats2half2_rn(v.x, v.y);
        __half2 h1 = __floats2half2_rn(v.z, v.w);
        uint2 pk;
        pk.x = *(unsigned*)&h0;
        pk.y = *(unsigned*)&h1;
        *(uint2*)&xh[row * XH_LD + c4] = pk;
    }
    // W -> fp16 smem: wh[k][col], col 0..63 Wl, 64..127 Wr
    for (int g = tid; g < 2048; g += 256) {
        int k = g >> 5;
        int c4 = (g & 31) << 2;
        float4 v = (c4 < 64) ? *(const float4*)&Wl[k * 64 + c4]
                             : *(const float4*)&Wr[k * 64 + (c4 - 64)];
        __half2 h0 = __floats2half2_rn(v.x, v.y);
        __half2 h1 = __floats2half2_rn(v.z, v.w);
        uint2 pk;
        pk.x = *(unsigned*)&h0;
        pk.y = *(unsigned*)&h1;
        *(uint2*)&wh[k * W_LD + c4] = pk;
    }
    __syncthreads();

    int warp = tid >> 5;
    int wr = warp >> 2;        // 0..1 : row block (64 rows)
    int wc = warp & 3;         // 0..3 : col block (32 cols)

    if (wc < 2) {
        // ---- xl: fp16 accumulators, direct store to g_xlh ----
        wmma::fragment<wmma::accumulator, 16, 16, 16, __half> cf[4][2];
#pragma unroll
        for (int i = 0; i < 4; i++)
#pragma unroll
            for (int j = 0; j < 2; j++)
                wmma::fill_fragment(cf[i][j], __float2half(0.f));

#pragma unroll
        for (int kk = 0; kk < 64; kk += 16) {
            wmma::fragment<wmma::matrix_a, 16, 16, 16, __half, wmma::row_major> af[4];
            wmma::fragment<wmma::matrix_b, 16, 16, 16, __half, wmma::row_major> bf[2];
#pragma unroll
            for (int i = 0; i < 4; i++)
                wmma::load_matrix_sync(af[i], &xh[(wr * 64 + i * 16) * XH_LD + kk], XH_LD);
#pragma unroll
            for (int j = 0; j < 2; j++)
                wmma::load_matrix_sync(bf[j], &wh[kk * W_LD + wc * 32 + j * 16], W_LD);
#pragma unroll
            for (int i = 0; i < 4; i++)
#pragma unroll
                for (int j = 0; j < 2; j++)
                    wmma::mma_sync(cf[i][j], af[i], bf[j], cf[i][j]);
        }

        int colBase = wc * 32;
#pragma unroll
        for (int i = 0; i < 4; i++) {
            int gr = nodeBase + wr * 64 + i * 16;
#pragma unroll
            for (int j = 0; j < 2; j++)
                wmma::store_matrix_sync(&g_xlh[(size_t)gr * DD + colBase + j * 16],
                                        cf[i][j], DD, wmma::mem_row_major);
        }
    } else {
        // ---- xr: fp32 accumulators, direct store to g_xr ----
        wmma::fragment<wmma::accumulator, 16, 16, 16, float> cf[4][2];
#pragma unroll
        for (int i = 0; i < 4; i++)
#pragma unroll
            for (int j = 0; j < 2; j++) wmma::fill_fragment(cf[i][j], 0.f);

#pragma unroll
        for (int kk = 0; kk < 64; kk += 16) {
            wmma::fragment<wmma::matrix_a, 16, 16, 16, __half, wmma::row_major> af[4];
            wmma::fragment<wmma::matrix_b, 16, 16, 16, __half, wmma::row_major> bf[2];
#pragma unroll
            for (int i = 0; i < 4; i++)
                wmma::load_matrix_sync(af[i], &xh[(wr * 64 + i * 16) * XH_LD + kk], XH_LD);
#pragma unroll
            for (int j = 0; j < 2; j++)
                wmma::load_matrix_sync(bf[j], &wh[kk * W_LD + wc * 32 + j * 16], W_LD);
#pragma unroll
            for (int i = 0; i < 4; i++)
#pragma unroll
                for (int j = 0; j < 2; j++)
                    wmma::mma_sync(cf[i][j], af[i], bf[j], cf[i][j]);
        }

        int colBase = wc * 32 - 64;
#pragma unroll
        for (int i = 0; i < 4; i++) {
            int gr = nodeBase + wr * 64 + i * 16;
#pragma unroll
            for (int j = 0; j < 2; j++)
                wmma::store_matrix_sync(&g_xr[(size_t)gr * DD + colBase + j * 16],
                                        cf[i][j], DD, wmma::mem_row_major);
        }
    }
}

// ------------------------- CSR build (once per launch) ----------------------
__global__ __launch_bounds__(SCAN_BLK) void k_scan1(int n) {
    __shared__ int sh[SCAN_BLK];
    int blk = blockIdx.x;
    int base = blk * SCAN_TILE + threadIdx.x * SCAN_ELEM;
    int t = threadIdx.x;
    int v[SCAN_ELEM];
    int sum = 0;
#pragma unroll
    for (int i = 0; i < SCAN_ELEM; i++) {
        int idx = base + i;
        v[i] = (idx < n) ? g_cnt[idx] : 0;
        if (idx < n) g_cnt[idx] = 0;
        sum += v[i];
    }
    sh[t] = sum;
    __syncthreads();
    for (int o = 1; o < SCAN_BLK; o <<= 1) {
        int x = (t >= o) ? sh[t - o] : 0;
        __syncthreads();
        sh[t] += x;
        __syncthreads();
    }
    int run = (t > 0) ? sh[t - 1] : 0;
    if (t == SCAN_BLK - 1) {
        int total = sh[SCAN_BLK - 1];
        for (int j = blk + 1; j < gridDim.x; j++) atomicAdd(&g_pre[j], total);
    }
#pragma unroll
    for (int i = 0; i < SCAN_ELEM; i++) {
        int idx = base + i;
        if (idx < n) { g_rowptr[idx] = run; g_ofs[idx] = run; }
        if (idx == n - 1) g_rowptr[n] = run + v[i];
        run += v[i];
    }
}

__global__ void k_scatter(const int* __restrict__ ei, int E) {
    int e = blockIdx.x * blockDim.x + threadIdx.x;
    if (e < E) {
        int d = ei[E + e];
        int pos = atomicAdd(&g_ofs[d], 1) + __ldg(&g_pre[d >> 12]);
        g_ssrc[pos] = ei[e];
    }
}

// ---------------------------------------------------------------------------
// Fused aggregation (unchanged): half-warp per dst node, 4 ch/lane.
// ---------------------------------------------------------------------------
__device__ __forceinline__ void edge_accum(int s, int j, unsigned mask16,
                                           const float4& xr4,
                                           const float4& a6, const float4& a4,
                                           float& acc0, float& acc1,
                                           float& acc2, float& acc3,
                                           float& den) {
    uint2 raw = *(const uint2*)&g_xlh[(size_t)s * DD + j];
    float2 a01 = __half22float2(*(__half2*)&raw.x);
    float2 a23 = __half22float2(*(__half2*)&raw.y);

    float m0 = a01.x + xr4.x;
    float m1 = a01.y + xr4.y;
    float m2 = a23.x + xr4.z;
    float m3 = a23.y + xr4.w;

    float part = m0 * a6.x;
    part = fmaf(fabsf(m0), a4.x, part);
    part = fmaf(m1, a6.y, part);
    part = fmaf(fabsf(m1), a4.y, part);
    part = fmaf(m2, a6.z, part);
    part = fmaf(fabsf(m2), a4.z, part);
    part = fmaf(m3, a6.w, part);
    part = fmaf(fabsf(m3), a4.w, part);

    part += __shfl_xor_sync(mask16, part, 1, 16);
    part += __shfl_xor_sync(mask16, part, 2, 16);

    float p = __expf(part);
    acc0 = fmaf(p, a01.x, acc0);
    acc1 = fmaf(p, a01.y, acc1);
    acc2 = fmaf(p, a23.x, acc2);
    acc3 = fmaf(p, a23.y, acc3);
    den += p;
}

__global__ __launch_bounds__(256) void k_agg(const float* __restrict__ xres,
                                             const float* __restrict__ att,
                                             const float* __restrict__ bias,
                                             const float* __restrict__ gamma,
                                             const float* __restrict__ beta,
                                             float* __restrict__ out, int n) {
    int warp = (blockIdx.x * blockDim.x + threadIdx.x) >> 5;
    int lane = threadIdx.x & 31;
    int hf = lane >> 4;
    int l16 = lane & 15;
    int d = warp * 2 + hf;
    if (d >= n) return;
    unsigned mask16 = hf ? 0xFFFF0000u : 0x0000FFFFu;
    int j = l16 * 4;

    float4 xr4 = *(const float4*)&g_xr[(size_t)d * DD + j];
    float4 at4 = *(const float4*)(att + j);
    float4 a6 = make_float4(0.6f * at4.x, 0.6f * at4.y, 0.6f * at4.z, 0.6f * at4.w);
    float4 a4 = make_float4(0.4f * at4.x, 0.4f * at4.y, 0.4f * at4.z, 0.4f * at4.w);

    float acc0 = 0.f, acc1 = 0.f, acc2 = 0.f, acc3 = 0.f, den = 0.f;

    // self loop
    edge_accum(d, j, mask16, xr4, a6, a4, acc0, acc1, acc2, acc3, den);

    int pre0 = __ldg(&g_pre[d >> 12]);
    int pre1 = __ldg(&g_pre[(d + 1) >> 12]);
    int begin = g_rowptr[d] + pre0;
    int end = g_rowptr[d + 1] + pre1;

    for (int base = begin; base < end; base += 16) {
        int idx = base + l16;
        int sv = (idx < end) ? g_ssrc[idx] : 0;
        int cnt = end - base;
        if (cnt > 16) cnt = 16;
#pragma unroll 4
        for (int k = 0; k < cnt; k++) {
            int s = __shfl_sync(mask16, sv, k, 16);
            edge_accum(s, j, mask16, xr4, a6, a4, acc0, acc1, acc2, acc3, den);
        }
    }

    // normalize + bias + residual
    float inv = 1.f / den;
    float4 xv = *(const float4*)&xres[(size_t)d * DD + j];
    float4 bi = *(const float4*)(bias + j);
    float v0 = acc0 * inv + bi.x + xv.x;
    float v1 = acc1 * inv + bi.y + xv.y;
    float v2 = acc2 * inv + bi.z + xv.z;
    float v3 = acc3 * inv + bi.w + xv.w;

    // LayerNorm over 64 ch (16-lane reduce)
    float s = v0 + v1 + v2 + v3;
    float s2 = v0 * v0 + v1 * v1 + v2 * v2 + v3 * v3;
#pragma unroll
    for (int o = 8; o; o >>= 1) {
        s += __shfl_xor_sync(mask16, s, o, 16);
        s2 += __shfl_xor_sync(mask16, s2, o, 16);
    }
    float mu = s * (1.f / 64.f);
    float var = s2 * (1.f / 64.f) - mu * mu;
    float rstd = rsqrtf(var + 1e-5f);

    float4 ga = *(const float4*)(gamma + j);
    float4 be = *(const float4*)(beta + j);
    float y0 = (v0 - mu) * rstd * ga.x + be.x;
    float y1 = (v1 - mu) * rstd * ga.y + be.y;
    float y2 = (v2 - mu) * rstd * ga.z + be.z;
    float y3 = (v3 - mu) * rstd * ga.w + be.w;

    const float ks = 0.70710678118654752f;
    y0 = 0.5f * y0 * (1.f + erff(y0 * ks));
    y1 = 0.5f * y1 * (1.f + erff(y1 * ks));
    y2 = 0.5f * y2 * (1.f + erff(y2 * ks));
    y3 = 0.5f * y3 * (1.f + erff(y3 * ks));

    *(float4*)&out[(size_t)d * DD + j] = make_float4(y0, y1, y2, y3);
}

// ---------------------------------------------------------------------------
extern "C" void kernel_launch(void* const* d_in, const int* in_sizes, int n_in,
                              void* d_out, int out_size) {
    const float* x = (const float*)d_in[0];
    const int* ei = (const int*)d_in[1];   // int32: [src(E), dst(E)]
    const float* Wl = (const float*)d_in[2];
    const float* Wr = (const float*)d_in[3];
    const float* att = (const float*)d_in[4];
    const float* bias = (const float*)d_in[5];
    const float* gamma = (const float*)d_in[6];
    const float* beta = (const float*)d_in[7];

    int n = in_sizes[0] / DD;
    int E = in_sizes[1] / 2;
    int Lnum = in_sizes[2] / (DD * DD);

    float *b0p = nullptr, *b1p = nullptr;
    cudaGetSymbolAddress((void**)&b0p, g_b0);
    cudaGetSymbolAddress((void**)&b1p, g_b1);

    const int gemmSmem = 128 * XH_LD * 2 + 64 * W_LD * 2;  // 35840

    static int attr_set = 0;
    if (!attr_set) {
        cudaFuncSetAttribute(k_gemm, cudaFuncAttributeMaxDynamicSharedMemorySize, gemmSmem);
        cudaFuncSetAttribute(k_agg, cudaFuncAttributePreferredSharedMemoryCarveout, 0);
        attr_set = 1;
    }

    int nbScan = (n + SCAN_TILE - 1) / SCAN_TILE;
    const float* cur = x;
    int aggBlocks = (n + 15) / 16;

    for (int i = 0; i < Lnum; i++) {
        // layer-0 order: gemm+hist(0), scan1(1), scatter(2), agg(3)
        k_gemm<<<(n + 127) / 128, 256, gemmSmem>>>(cur, Wl + (size_t)i * DD * DD,
                                                   Wr + (size_t)i * DD * DD, n,
                                                   ei, E, i == 0 ? 1 : 0);
        if (i == 0) {
            k_scan1<<<nbScan, SCAN_BLK>>>(n);
            k_scatter<<<(E + 255) / 256, 256>>>(ei, E);
        }

        float* outp;
        if (i == Lnum - 1) outp = (float*)d_out;
        else outp = (i & 1) ? b1p : b0p;

        k_agg<<<aggBlocks, 256>>>(cur, att + (size_t)i * DD,
                                  bias + (size_t)i * DD,
                                  gamma + (size_t)i * DD,
                                  beta + (size_t)i * DD,
                                  outp, n);
        cur = outp;
    }
}

// round 12
// speedup vs baseline: 3.3203x; 1.0665x over previous
#include <cuda_runtime.h>
#include <cuda_fp16.h>
#include <mma.h>
#include <math.h>

using namespace nvcuda;

// GATv2 (L=3, H=4, C=16, D=64), N=100000, E=1280000 (+N self loops).
// R12:
//  - agg edge math in packed fp16: half2 logits (hadd2/habs2/hfma2) and
//    half2 accumulators (den fp32); sv prefetch. ~26% fewer warp instrs.
//  - gemm / CSR unchanged from R11.
//  - launch order: gemm+hist(0), scan1(1), scatter(2), agg(3).

#define NNODES 100000
#define NEDGES 1280000
#define DD 64
#define XH_LD 72     // halves per row, x tile
#define W_LD 136     // halves per row, W tile
#define SCAN_BLK 512
#define SCAN_ELEM 8
#define SCAN_TILE (SCAN_BLK * SCAN_ELEM)  // 4096

__device__ __align__(128) __half g_xlh[(NNODES + 128) * DD];  // +128 rows: wmma overhang
__device__ __align__(128) float g_xr[(NNODES + 128) * DD];    // +128 rows: wmma overhang
__device__ __align__(16) float g_b0[NNODES * DD];
__device__ __align__(16) float g_b1[NNODES * DD];
__device__ int g_cnt[NNODES];      // zero at load; scan1 re-zeroes after reading
__device__ int g_ofs[NNODES];
__device__ int g_rowptr[NNODES + 1];
__device__ int g_pre[32];          // zeroed by layer-0 gemm each replay
__device__ int g_ssrc[NEDGES];

// ---------------------------------------------------------------------------
// Tensor-core GEMM (unchanged from R11).
// ---------------------------------------------------------------------------
__global__ __launch_bounds__(256) void k_gemm(const float* __restrict__ x,
                                              const float* __restrict__ Wl,
                                              const float* __restrict__ Wr,
                                              int n,
                                              const int* __restrict__ ei,
                                              int E, int do_csr) {
    extern __shared__ char smraw[];
    __half* xh = (__half*)smraw;                          // [128][XH_LD]
    __half* wh = (__half*)(smraw + 128 * XH_LD * 2);      // [64][W_LD]

    int tid = threadIdx.x;
    int nodeBase = blockIdx.x * 128;

    if (do_csr) {
        if (blockIdx.x == 0 && tid < 32) g_pre[tid] = 0;
        int stride = gridDim.x * blockDim.x;
        for (int e = blockIdx.x * blockDim.x + tid; e < E; e += stride)
            atomicAdd(&g_cnt[ei[E + e]], 1);
    }

    for (int g = tid; g < 2048; g += 256) {
        int row = g >> 4;
        int c4 = (g & 15) << 2;
        int gn = nodeBase + row;
        float4 v = (gn < n) ? *(const float4*)&x[(size_t)gn * DD + c4]
                            : make_float4(0.f, 0.f, 0.f, 0.f);
        __half2 h0 = __floats2half2_rn(v.x, v.y);
        __half2 h1 = __floats2half2_rn(v.z, v.w);
        uint2 pk;
        pk.x = *(unsigned*)&h0;
        pk.y = *(unsigned*)&h1;
        *(uint2*)&xh[row * XH_LD + c4] = pk;
    }
    for (int g = tid; g < 2048; g += 256) {
        int k = g >> 5;
        int c4 = (g & 31) << 2;
        float4 v = (c4 < 64) ? *(const float4*)&Wl[k * 64 + c4]
                             : *(const float4*)&Wr[k * 64 + (c4 - 64)];
        __half2 h0 = __floats2half2_rn(v.x, v.y);
        __half2 h1 = __floats2half2_rn(v.z, v.w);
        uint2 pk;
        pk.x = *(unsigned*)&h0;
        pk.y = *(unsigned*)&h1;
        *(uint2*)&wh[k * W_LD + c4] = pk;
    }
    __syncthreads();

    int warp = tid >> 5;
    int wr = warp >> 2;
    int wc = warp & 3;

    if (wc < 2) {
        wmma::fragment<wmma::accumulator, 16, 16, 16, __half> cf[4][2];
#pragma unroll
        for (int i = 0; i < 4; i++)
#pragma unroll
            for (int j = 0; j < 2; j++)
                wmma::fill_fragment(cf[i][j], __float2half(0.f));

#pragma unroll
        for (int kk = 0; kk < 64; kk += 16) {
            wmma::fragment<wmma::matrix_a, 16, 16, 16, __half, wmma::row_major> af[4];
            wmma::fragment<wmma::matrix_b, 16, 16, 16, __half, wmma::row_major> bf[2];
#pragma unroll
            for (int i = 0; i < 4; i++)
                wmma::load_matrix_sync(af[i], &xh[(wr * 64 + i * 16) * XH_LD + kk], XH_LD);
#pragma unroll
            for (int j = 0; j < 2; j++)
                wmma::load_matrix_sync(bf[j], &wh[kk * W_LD + wc * 32 + j * 16], W_LD);
#pragma unroll
            for (int i = 0; i < 4; i++)
#pragma unroll
                for (int j = 0; j < 2; j++)
                    wmma::mma_sync(cf[i][j], af[i], bf[j], cf[i][j]);
        }

        int colBase = wc * 32;
#pragma unroll
        for (int i = 0; i < 4; i++) {
            int gr = nodeBase + wr * 64 + i * 16;
#pragma unroll
            for (int j = 0; j < 2; j++)
                wmma::store_matrix_sync(&g_xlh[(size_t)gr * DD + colBase + j * 16],
                                        cf[i][j], DD, wmma::mem_row_major);
        }
    } else {
        wmma::fragment<wmma::accumulator, 16, 16, 16, float> cf[4][2];
#pragma unroll
        for (int i = 0; i < 4; i++)
#pragma unroll
            for (int j = 0; j < 2; j++) wmma::fill_fragment(cf[i][j], 0.f);

#pragma unroll
        for (int kk = 0; kk < 64; kk += 16) {
            wmma::fragment<wmma::matrix_a, 16, 16, 16, __half, wmma::row_major> af[4];
            wmma::fragment<wmma::matrix_b, 16, 16, 16, __half, wmma::row_major> bf[2];
#pragma unroll
            for (int i = 0; i < 4; i++)
                wmma::load_matrix_sync(af[i], &xh[(wr * 64 + i * 16) * XH_LD + kk], XH_LD);
#pragma unroll
            for (int j = 0; j < 2; j++)
                wmma::load_matrix_sync(bf[j], &wh[kk * W_LD + wc * 32 + j * 16], W_LD);
#pragma unroll
            for (int i = 0; i < 4; i++)
#pragma unroll
                for (int j = 0; j < 2; j++)
                    wmma::mma_sync(cf[i][j], af[i], bf[j], cf[i][j]);
        }

        int colBase = wc * 32 - 64;
#pragma unroll
        for (int i = 0; i < 4; i++) {
            int gr = nodeBase + wr * 64 + i * 16;
#pragma unroll
            for (int j = 0; j < 2; j++)
                wmma::store_matrix_sync(&g_xr[(size_t)gr * DD + colBase + j * 16],
                                        cf[i][j], DD, wmma::mem_row_major);
        }
    }
}

// ------------------------- CSR build (once per launch) ----------------------
__global__ __launch_bounds__(SCAN_BLK) void k_scan1(int n) {
    __shared__ int sh[SCAN_BLK];
    int blk = blockIdx.x;
    int base = blk * SCAN_TILE + threadIdx.x * SCAN_ELEM;
    int t = threadIdx.x;
    int v[SCAN_ELEM];
    int sum = 0;
#pragma unroll
    for (int i = 0; i < SCAN_ELEM; i++) {
        int idx = base + i;
        v[i] = (idx < n) ? g_cnt[idx] : 0;
        if (idx < n) g_cnt[idx] = 0;
        sum += v[i];
    }
    sh[t] = sum;
    __syncthreads();
    for (int o = 1; o < SCAN_BLK; o <<= 1) {
        int x = (t >= o) ? sh[t - o] : 0;
        __syncthreads();
        sh[t] += x;
        __syncthreads();
    }
    int run = (t > 0) ? sh[t - 1] : 0;
    if (t == SCAN_BLK - 1) {
        int total = sh[SCAN_BLK - 1];
        for (int j = blk + 1; j < gridDim.x; j++) atomicAdd(&g_pre[j], total);
    }
#pragma unroll
    for (int i = 0; i < SCAN_ELEM; i++) {
        int idx = base + i;
        if (idx < n) { g_rowptr[idx] = run; g_ofs[idx] = run; }
        if (idx == n - 1) g_rowptr[n] = run + v[i];
        run += v[i];
    }
}

__global__ void k_scatter(const int* __restrict__ ei, int E) {
    int e = blockIdx.x * blockDim.x + threadIdx.x;
    if (e < E) {
        int d = ei[E + e];
        int pos = atomicAdd(&g_ofs[d], 1) + __ldg(&g_pre[d >> 12]);
        g_ssrc[pos] = ei[e];
    }
}

// ---------------------------------------------------------------------------
// Fused aggregation: half-warp per dst node, 4 ch/lane.
// Edge math in packed fp16; den in fp32.
// ---------------------------------------------------------------------------
__device__ __forceinline__ void edge_accum_h(int s, int j, unsigned mask16,
                                             __half2 xr01, __half2 xr23,
                                             __half2 a601, __half2 a623,
                                             __half2 a401, __half2 a423,
                                             __half2& acc01, __half2& acc23,
                                             float& den) {
    uint2 raw = *(const uint2*)&g_xlh[(size_t)s * DD + j];
    __half2 a01 = *(__half2*)&raw.x;
    __half2 a23 = *(__half2*)&raw.y;

    __half2 m01 = __hadd2(a01, xr01);
    __half2 m23 = __hadd2(a23, xr23);

    __half2 t = __hmul2(__habs2(m01), a401);
    t = __hfma2(m01, a601, t);
    t = __hfma2(__habs2(m23), a423, t);
    t = __hfma2(m23, a623, t);

    float2 pf = __half22float2(t);
    float part = pf.x + pf.y;
    part += __shfl_xor_sync(mask16, part, 1, 16);
    part += __shfl_xor_sync(mask16, part, 2, 16);

    float p = __expf(part);
    __half2 ph = __float2half2_rn(p);
    acc01 = __hfma2(ph, a01, acc01);
    acc23 = __hfma2(ph, a23, acc23);
    den += p;
}

__global__ __launch_bounds__(256) void k_agg(const float* __restrict__ xres,
                                             const float* __restrict__ att,
                                             const float* __restrict__ bias,
                                             const float* __restrict__ gamma,
                                             const float* __restrict__ beta,
                                             float* __restrict__ out, int n) {
    int warp = (blockIdx.x * blockDim.x + threadIdx.x) >> 5;
    int lane = threadIdx.x & 31;
    int hf = lane >> 4;
    int l16 = lane & 15;
    int d = warp * 2 + hf;
    if (d >= n) return;
    unsigned mask16 = hf ? 0xFFFF0000u : 0x0000FFFFu;
    int j = l16 * 4;

    float4 xr4 = *(const float4*)&g_xr[(size_t)d * DD + j];
    float4 at4 = *(const float4*)(att + j);
    __half2 xr01 = __floats2half2_rn(xr4.x, xr4.y);
    __half2 xr23 = __floats2half2_rn(xr4.z, xr4.w);
    __half2 a601 = __floats2half2_rn(0.6f * at4.x, 0.6f * at4.y);
    __half2 a623 = __floats2half2_rn(0.6f * at4.z, 0.6f * at4.w);
    __half2 a401 = __floats2half2_rn(0.4f * at4.x, 0.4f * at4.y);
    __half2 a423 = __floats2half2_rn(0.4f * at4.z, 0.4f * at4.w);

    __half2 acc01 = __float2half2_rn(0.f);
    __half2 acc23 = __float2half2_rn(0.f);
    float den = 0.f;

    // self loop
    edge_accum_h(d, j, mask16, xr01, xr23, a601, a623, a401, a423,
                 acc01, acc23, den);

    int pre0 = __ldg(&g_pre[d >> 12]);
    int pre1 = __ldg(&g_pre[(d + 1) >> 12]);
    int begin = g_rowptr[d] + pre0;
    int end = g_rowptr[d + 1] + pre1;

    int svNext = (begin + l16 < end) ? g_ssrc[begin + l16] : 0;

    for (int base = begin; base < end; base += 16) {
        int sv = svNext;
        int nidx = base + 16 + l16;
        svNext = (nidx < end) ? g_ssrc[nidx] : 0;
        int cnt = end - base;
        if (cnt > 16) cnt = 16;
#pragma unroll 4
        for (int k = 0; k < cnt; k++) {
            int s = __shfl_sync(mask16, sv, k, 16);
            edge_accum_h(s, j, mask16, xr01, xr23, a601, a623, a401, a423,
                         acc01, acc23, den);
        }
    }

    // normalize + bias + residual (fp32 epilogue)
    float2 f01 = __half22float2(acc01);
    float2 f23 = __half22float2(acc23);
    float inv = 1.f / den;
    float4 xv = *(const float4*)&xres[(size_t)d * DD + j];
    float4 bi = *(const float4*)(bias + j);
    float v0 = f01.x * inv + bi.x + xv.x;
    float v1 = f01.y * inv + bi.y + xv.y;
    float v2 = f23.x * inv + bi.z + xv.z;
    float v3 = f23.y * inv + bi.w + xv.w;

    // LayerNorm over 64 ch (16-lane reduce)
    float s = v0 + v1 + v2 + v3;
    float s2 = v0 * v0 + v1 * v1 + v2 * v2 + v3 * v3;
#pragma unroll
    for (int o = 8; o; o >>= 1) {
        s += __shfl_xor_sync(mask16, s, o, 16);
        s2 += __shfl_xor_sync(mask16, s2, o, 16);
    }
    float mu = s * (1.f / 64.f);
    float var = s2 * (1.f / 64.f) - mu * mu;
    float rstd = rsqrtf(var + 1e-5f);

    float4 ga = *(const float4*)(gamma + j);
    float4 be = *(const float4*)(beta + j);
    float y0 = (v0 - mu) * rstd * ga.x + be.x;
    float y1 = (v1 - mu) * rstd * ga.y + be.y;
    float y2 = (v2 - mu) * rstd * ga.z + be.z;
    float y3 = (v3 - mu) * rstd * ga.w + be.w;

    const float ks = 0.70710678118654752f;
    y0 = 0.5f * y0 * (1.f + erff(y0 * ks));
    y1 = 0.5f * y1 * (1.f + erff(y1 * ks));
    y2 = 0.5f * y2 * (1.f + erff(y2 * ks));
    y3 = 0.5f * y3 * (1.f + erff(y3 * ks));

    *(float4*)&out[(size_t)d * DD + j] = make_float4(y0, y1, y2, y3);
}

// ---------------------------------------------------------------------------
extern "C" void kernel_launch(void* const* d_in, const int* in_sizes, int n_in,
                              void* d_out, int out_size) {
    const float* x = (const float*)d_in[0];
    const int* ei = (const int*)d_in[1];   // int32: [src(E), dst(E)]
    const float* Wl = (const float*)d_in[2];
    const float* Wr = (const float*)d_in[3];
    const float* att = (const float*)d_in[4];
    const float* bias = (const float*)d_in[5];
    const float* gamma = (const float*)d_in[6];
    const float* beta = (const float*)d_in[7];

    int n = in_sizes[0] / DD;
    int E = in_sizes[1] / 2;
    int Lnum = in_sizes[2] / (DD * DD);

    float *b0p = nullptr, *b1p = nullptr;
    cudaGetSymbolAddress((void**)&b0p, g_b0);
    cudaGetSymbolAddress((void**)&b1p, g_b1);

    const int gemmSmem = 128 * XH_LD * 2 + 64 * W_LD * 2;  // 35840

    static int attr_set = 0;
    if (!attr_set) {
        cudaFuncSetAttribute(k_gemm, cudaFuncAttributeMaxDynamicSharedMemorySize, gemmSmem);
        cudaFuncSetAttribute(k_agg, cudaFuncAttributePreferredSharedMemoryCarveout, 0);
        attr_set = 1;
    }

    int nbScan = (n + SCAN_TILE - 1) / SCAN_TILE;
    const float* cur = x;
    int aggBlocks = (n + 15) / 16;

    for (int i = 0; i < Lnum; i++) {
        k_gemm<<<(n + 127) / 128, 256, gemmSmem>>>(cur, Wl + (size_t)i * DD * DD,
                                                   Wr + (size_t)i * DD * DD, n,
                                                   ei, E, i == 0 ? 1 : 0);
        if (i == 0) {
            k_scan1<<<nbScan, SCAN_BLK>>>(n);
            k_scatter<<<(E + 255) / 256, 256>>>(ei, E);
        }

        float* outp;
        if (i == Lnum - 1) outp = (float*)d_out;
        else outp = (i & 1) ? b1p : b0p;

        k_agg<<<aggBlocks, 256>>>(cur, att + (size_t)i * DD,
                                  bias + (size_t)i * DD,
                                  gamma + (size_t)i * DD,
                                  beta + (size_t)i * DD,
                                  outp, n);
        cur = outp;
    }
}

// round 13
// speedup vs baseline: 3.3532x; 1.0099x over previous
#include <cuda_runtime.h>
#include <cuda_fp16.h>
#include <mma.h>
#include <math.h>

using namespace nvcuda;

// GATv2 (L=3, H=4, C=16, D=64), N=100000, E=1280000 (+N self loops).
// R13:
//  - nodes counting-sorted by in-degree; agg processes perm[] order so the two
//    16-lane halves of each warp get equal-degree nodes (no divergence, no
//    straggler blocks). Output still indexed by node -> deterministic.
//  - xr stored fp16 (gemm xl/xr paths identical, fp16 accumulators).
//  - agg edge math in packed fp16 (R12), den fp32.

#define NNODES 100000
#define NEDGES 1280000
#define DD 64
#define XH_LD 72     // halves per row, x tile
#define W_LD 136     // halves per row, W tile
#define SCAN_BLK 512
#define SCAN_ELEM 8
#define SCAN_TILE (SCAN_BLK * SCAN_ELEM)  // 4096

__device__ __align__(128) __half g_xlh[(NNODES + 128) * DD];  // +128 rows: wmma overhang
__device__ __align__(128) __half g_xrh[(NNODES + 128) * DD];  // +128 rows: wmma overhang
__device__ __align__(16) float g_b0[NNODES * DD];
__device__ __align__(16) float g_b1[NNODES * DD];
__device__ int g_cnt[NNODES];      // zero at load; scan1 re-zeroes after reading
__device__ int g_ofs[NNODES];
__device__ int g_rowptr[NNODES + 1];
__device__ int g_pre[32];          // zeroed by layer-0 gemm each replay
__device__ int g_ssrc[NEDGES];
__device__ int g_perm[NNODES];
__device__ int g_dhist[512];       // zeroed by layer-0 gemm each replay
__device__ int g_dbase[512];

// ---------------------------------------------------------------------------
// Tensor-core GEMM: [128 nodes] x [128 cols] per block. 8 warps, each 64x32.
// Both xl (cols 0..63) and xr (64..127) use fp16 accumulators, direct store.
// Layer 0 (do_csr): zero g_pre/g_dhist + histogram dst into g_cnt.
// ---------------------------------------------------------------------------
__global__ __launch_bounds__(256) void k_gemm(const float* __restrict__ x,
                                              const float* __restrict__ Wl,
                                              const float* __restrict__ Wr,
                                              int n,
                                              const int* __restrict__ ei,
                                              int E, int do_csr) {
    extern __shared__ char smraw[];
    __half* xh = (__half*)smraw;                          // [128][XH_LD]
    __half* wh = (__half*)(smraw + 128 * XH_LD * 2);      // [64][W_LD]

    int tid = threadIdx.x;
    int nodeBase = blockIdx.x * 128;

    if (do_csr) {
        if (blockIdx.x == 0) {
            if (tid < 32) g_pre[tid] = 0;
            g_dhist[tid] = 0;
            g_dhist[tid + 256] = 0;
        }
        int stride = gridDim.x * blockDim.x;
        for (int e = blockIdx.x * blockDim.x + tid; e < E; e += stride)
            atomicAdd(&g_cnt[ei[E + e]], 1);
    }

    for (int g = tid; g < 2048; g += 256) {
        int row = g >> 4;
        int c4 = (g & 15) << 2;
        int gn = nodeBase + row;
        float4 v = (gn < n) ? *(const float4*)&x[(size_t)gn * DD + c4]
                            : make_float4(0.f, 0.f, 0.f, 0.f);
        __half2 h0 = __floats2half2_rn(v.x, v.y);
        __half2 h1 = __floats2half2_rn(v.z, v.w);
        uint2 pk;
        pk.x = *(unsigned*)&h0;
        pk.y = *(unsigned*)&h1;
        *(uint2*)&xh[row * XH_LD + c4] = pk;
    }
    for (int g = tid; g < 2048; g += 256) {
        int k = g >> 5;
        int c4 = (g & 31) << 2;
        float4 v = (c4 < 64) ? *(const float4*)&Wl[k * 64 + c4]
                             : *(const float4*)&Wr[k * 64 + (c4 - 64)];
        __half2 h0 = __floats2half2_rn(v.x, v.y);
        __half2 h1 = __floats2half2_rn(v.z, v.w);
        uint2 pk;
        pk.x = *(unsigned*)&h0;
        pk.y = *(unsigned*)&h1;
        *(uint2*)&wh[k * W_LD + c4] = pk;
    }
    __syncthreads();

    int warp = tid >> 5;
    int wr = warp >> 2;
    int wc = warp & 3;

    wmma::fragment<wmma::accumulator, 16, 16, 16, __half> cf[4][2];
#pragma unroll
    for (int i = 0; i < 4; i++)
#pragma unroll
        for (int j = 0; j < 2; j++)
            wmma::fill_fragment(cf[i][j], __float2half(0.f));

#pragma unroll
    for (int kk = 0; kk < 64; kk += 16) {
        wmma::fragment<wmma::matrix_a, 16, 16, 16, __half, wmma::row_major> af[4];
        wmma::fragment<wmma::matrix_b, 16, 16, 16, __half, wmma::row_major> bf[2];
#pragma unroll
        for (int i = 0; i < 4; i++)
            wmma::load_matrix_sync(af[i], &xh[(wr * 64 + i * 16) * XH_LD + kk], XH_LD);
#pragma unroll
        for (int j = 0; j < 2; j++)
            wmma::load_matrix_sync(bf[j], &wh[kk * W_LD + wc * 32 + j * 16], W_LD);
#pragma unroll
        for (int i = 0; i < 4; i++)
#pragma unroll
            for (int j = 0; j < 2; j++)
                wmma::mma_sync(cf[i][j], af[i], bf[j], cf[i][j]);
    }

    __half* dstBase = (wc < 2) ? g_xlh : g_xrh;
    int colBase = (wc < 2) ? wc * 32 : wc * 32 - 64;
#pragma unroll
    for (int i = 0; i < 4; i++) {
        int gr = nodeBase + wr * 64 + i * 16;
#pragma unroll
        for (int j = 0; j < 2; j++)
            wmma::store_matrix_sync(&dstBase[(size_t)gr * DD + colBase + j * 16],
                                    cf[i][j], DD, wmma::mem_row_major);
    }
}

// ------------------------- CSR build (once per launch) ----------------------
// scan1 also histograms degrees into g_dhist (bin = min(deg,511)).
__global__ __launch_bounds__(SCAN_BLK) void k_scan1(int n) {
    __shared__ int sh[SCAN_BLK];
    int blk = blockIdx.x;
    int base = blk * SCAN_TILE + threadIdx.x * SCAN_ELEM;
    int t = threadIdx.x;
    int v[SCAN_ELEM];
    int sum = 0;
#pragma unroll
    for (int i = 0; i < SCAN_ELEM; i++) {
        int idx = base + i;
        v[i] = (idx < n) ? g_cnt[idx] : 0;
        if (idx < n) {
            g_cnt[idx] = 0;
            int bin = v[i] < 511 ? v[i] : 511;
            atomicAdd(&g_dhist[bin], 1);
        }
        sum += v[i];
    }
    sh[t] = sum;
    __syncthreads();
    for (int o = 1; o < SCAN_BLK; o <<= 1) {
        int x = (t >= o) ? sh[t - o] : 0;
        __syncthreads();
        sh[t] += x;
        __syncthreads();
    }
    int run = (t > 0) ? sh[t - 1] : 0;
    if (t == SCAN_BLK - 1) {
        int total = sh[SCAN_BLK - 1];
        for (int j = blk + 1; j < gridDim.x; j++) atomicAdd(&g_pre[j], total);
    }
#pragma unroll
    for (int i = 0; i < SCAN_ELEM; i++) {
        int idx = base + i;
        if (idx < n) { g_rowptr[idx] = run; g_ofs[idx] = run; }
        if (idx == n - 1) g_rowptr[n] = run + v[i];
        run += v[i];
    }
}

__global__ __launch_bounds__(512) void k_degscan() {
    __shared__ int sh[512];
    int t = threadIdx.x;
    sh[t] = g_dhist[t];
    __syncthreads();
    for (int o = 1; o < 512; o <<= 1) {
        int x = (t >= o) ? sh[t - o] : 0;
        __syncthreads();
        sh[t] += x;
        __syncthreads();
    }
    g_dbase[t] = (t > 0) ? sh[t - 1] : 0;
}

__global__ void k_degscatter(int n) {
    int d = blockIdx.x * blockDim.x + threadIdx.x;
    if (d < n) {
        int deg = (g_rowptr[d + 1] + __ldg(&g_pre[(d + 1) >> 12]))
                - (g_rowptr[d] + __ldg(&g_pre[d >> 12]));
        int bin = deg < 511 ? deg : 511;
        int pos = atomicAdd(&g_dbase[bin], 1);
        g_perm[pos] = d;
    }
}

__global__ void k_scatter(const int* __restrict__ ei, int E) {
    int e = blockIdx.x * blockDim.x + threadIdx.x;
    if (e < E) {
        int d = ei[E + e];
        int pos = atomicAdd(&g_ofs[d], 1) + __ldg(&g_pre[d >> 12]);
        g_ssrc[pos] = ei[e];
    }
}

// ---------------------------------------------------------------------------
// Fused aggregation: half-warp per dst node (degree-sorted perm order),
// 4 ch/lane, packed fp16 edge math, fp32 den + epilogue.
// ---------------------------------------------------------------------------
__device__ __forceinline__ void edge_accum_h(int s, int j, unsigned mask16,
                                             __half2 xr01, __half2 xr23,
                                             __half2 a601, __half2 a623,
                                             __half2 a401, __half2 a423,
                                             __half2& acc01, __half2& acc23,
                                             float& den) {
    uint2 raw = *(const uint2*)&g_xlh[(size_t)s * DD + j];
    __half2 a01 = *(__half2*)&raw.x;
    __half2 a23 = *(__half2*)&raw.y;

    __half2 m01 = __hadd2(a01, xr01);
    __half2 m23 = __hadd2(a23, xr23);

    __half2 t = __hmul2(__habs2(m01), a401);
    t = __hfma2(m01, a601, t);
    t = __hfma2(__habs2(m23), a423, t);
    t = __hfma2(m23, a623, t);

    float2 pf = __half22float2(t);
    float part = pf.x + pf.y;
    part += __shfl_xor_sync(mask16, part, 1, 16);
    part += __shfl_xor_sync(mask16, part, 2, 16);

    float p = __expf(part);
    __half2 ph = __float2half2_rn(p);
    acc01 = __hfma2(ph, a01, acc01);
    acc23 = __hfma2(ph, a23, acc23);
    den += p;
}

__global__ __launch_bounds__(256) void k_agg(const float* __restrict__ xres,
                                             const float* __restrict__ att,
                                             const float* __restrict__ bias,
                                             const float* __restrict__ gamma,
                                             const float* __restrict__ beta,
                                             float* __restrict__ out, int n) {
    int warp = (blockIdx.x * blockDim.x + threadIdx.x) >> 5;
    int lane = threadIdx.x & 31;
    int hf = lane >> 4;
    int l16 = lane & 15;
    int slot = warp * 2 + hf;
    if (slot >= n) return;
    int d = g_perm[slot];
    unsigned mask16 = hf ? 0xFFFF0000u : 0x0000FFFFu;
    int j = l16 * 4;

    uint2 rawr = *(const uint2*)&g_xrh[(size_t)d * DD + j];
    __half2 xr01 = *(__half2*)&rawr.x;
    __half2 xr23 = *(__half2*)&rawr.y;

    float4 at4 = *(const float4*)(att + j);
    __half2 a601 = __floats2half2_rn(0.6f * at4.x, 0.6f * at4.y);
    __half2 a623 = __floats2half2_rn(0.6f * at4.z, 0.6f * at4.w);
    __half2 a401 = __floats2half2_rn(0.4f * at4.x, 0.4f * at4.y);
    __half2 a423 = __floats2half2_rn(0.4f * at4.z, 0.4f * at4.w);

    __half2 acc01 = __float2half2_rn(0.f);
    __half2 acc23 = __float2half2_rn(0.f);
    float den = 0.f;

    // self loop
    edge_accum_h(d, j, mask16, xr01, xr23, a601, a623, a401, a423,
                 acc01, acc23, den);

    int pre0 = __ldg(&g_pre[d >> 12]);
    int pre1 = __ldg(&g_pre[(d + 1) >> 12]);
    int begin = g_rowptr[d] + pre0;
    int end = g_rowptr[d + 1] + pre1;

    int svNext = (begin + l16 < end) ? g_ssrc[begin + l16] : 0;

    for (int base = begin; base < end; base += 16) {
        int sv = svNext;
        int nidx = base + 16 + l16;
        svNext = (nidx < end) ? g_ssrc[nidx] : 0;
        int cnt = end - base;
        if (cnt > 16) cnt = 16;
#pragma unroll 4
        for (int k = 0; k < cnt; k++) {
            int s = __shfl_sync(mask16, sv, k, 16);
            edge_accum_h(s, j, mask16, xr01, xr23, a601, a623, a401, a423,
                         acc01, acc23, den);
        }
    }

    // normalize + bias + residual (fp32 epilogue)
    float2 f01 = __half22float2(acc01);
    float2 f23 = __half22float2(acc23);
    float inv = 1.f / den;
    float4 xv = *(const float4*)&xres[(size_t)d * DD + j];
    float4 bi = *(const float4*)(bias + j);
    float v0 = f01.x * inv + bi.x + xv.x;
    float v1 = f01.y * inv + bi.y + xv.y;
    float v2 = f23.x * inv + bi.z + xv.z;
    float v3 = f23.y * inv + bi.w + xv.w;

    // LayerNorm over 64 ch (16-lane reduce)
    float s = v0 + v1 + v2 + v3;
    float s2 = v0 * v0 + v1 * v1 + v2 * v2 + v3 * v3;
#pragma unroll
    for (int o = 8; o; o >>= 1) {
        s += __shfl_xor_sync(mask16, s, o, 16);
        s2 += __shfl_xor_sync(mask16, s2, o, 16);
    }
    float mu = s * (1.f / 64.f);
    float var = s2 * (1.f / 64.f) - mu * mu;
    float rstd = rsqrtf(var + 1e-5f);

    float4 ga = *(const float4*)(gamma + j);
    float4 be = *(const float4*)(beta + j);
    float y0 = (v0 - mu) * rstd * ga.x + be.x;
    float y1 = (v1 - mu) * rstd * ga.y + be.y;
    float y2 = (v2 - mu) * rstd * ga.z + be.z;
    float y3 = (v3 - mu) * rstd * ga.w + be.w;

    const float ks = 0.70710678118654752f;
    y0 = 0.5f * y0 * (1.f + erff(y0 * ks));
    y1 = 0.5f * y1 * (1.f + erff(y1 * ks));
    y2 = 0.5f * y2 * (1.f + erff(y2 * ks));
    y3 = 0.5f * y3 * (1.f + erff(y3 * ks));

    *(float4*)&out[(size_t)d * DD + j] = make_float4(y0, y1, y2, y3);
}

// ---------------------------------------------------------------------------
extern "C" void kernel_launch(void* const* d_in, const int* in_sizes, int n_in,
                              void* d_out, int out_size) {
    const float* x = (const float*)d_in[0];
    const int* ei = (const int*)d_in[1];   // int32: [src(E), dst(E)]
    const float* Wl = (const float*)d_in[2];
    const float* Wr = (const float*)d_in[3];
    const float* att = (const float*)d_in[4];
    const float* bias = (const float*)d_in[5];
    const float* gamma = (const float*)d_in[6];
    const float* beta = (const float*)d_in[7];

    int n = in_sizes[0] / DD;
    int E = in_sizes[1] / 2;
    int Lnum = in_sizes[2] / (DD * DD);

    float *b0p = nullptr, *b1p = nullptr;
    cudaGetSymbolAddress((void**)&b0p, g_b0);
    cudaGetSymbolAddress((void**)&b1p, g_b1);

    const int gemmSmem = 128 * XH_LD * 2 + 64 * W_LD * 2;  // 35840

    static int attr_set = 0;
    if (!attr_set) {
        cudaFuncSetAttribute(k_gemm, cudaFuncAttributeMaxDynamicSharedMemorySize, gemmSmem);
        cudaFuncSetAttribute(k_agg, cudaFuncAttributePreferredSharedMemoryCarveout, 0);
        attr_set = 1;
    }

    int nbScan = (n + SCAN_TILE - 1) / SCAN_TILE;
    const float* cur = x;
    int aggBlocks = (n + 15) / 16;

    for (int i = 0; i < Lnum; i++) {
        k_gemm<<<(n + 127) / 128, 256, gemmSmem>>>(cur, Wl + (size_t)i * DD * DD,
                                                   Wr + (size_t)i * DD * DD, n,
                                                   ei, E, i == 0 ? 1 : 0);
        if (i == 0) {
            k_scan1<<<nbScan, SCAN_BLK>>>(n);
            k_degscan<<<1, 512>>>();
            k_degscatter<<<(n + 255) / 256, 256>>>(n);
            k_scatter<<<(E + 255) / 256, 256>>>(ei, E);
        }

        float* outp;
        if (i == Lnum - 1) outp = (float*)d_out;
        else outp = (i & 1) ? b1p : b0p;

        k_agg<<<aggBlocks, 256>>>(cur, att + (size_t)i * DD,
                                  bias + (size_t)i * DD,
                                  gamma + (size_t)i * DD,
                                  beta + (size_t)i * DD,
                                  outp, n);
        cur = outp;
    }
}

// round 14
// speedup vs baseline: 3.7913x; 1.1306x over previous
#include <cuda_runtime.h>
#include <cuda_fp16.h>
#include <mma.h>
#include <math.h>

using namespace nvcuda;

// GATv2 (L=3, H=4, C=16, D=64), N=100000, E=1280000 (+N self loops).
// R14 = R13 with the degree-sort atomics fixed:
//  - scan1 builds the degree histogram in smem, flushes per-bin per-block
//  - degscatter uses block-aggregated ranges (1 global atomic per bin per
//    block) instead of 100k contended global atomics.

#define NNODES 100000
#define NEDGES 1280000
#define DD 64
#define XH_LD 72     // halves per row, x tile
#define W_LD 136     // halves per row, W tile
#define SCAN_BLK 512
#define SCAN_ELEM 8
#define SCAN_TILE (SCAN_BLK * SCAN_ELEM)  // 4096

__device__ __align__(128) __half g_xlh[(NNODES + 128) * DD];  // +128 rows: wmma overhang
__device__ __align__(128) __half g_xrh[(NNODES + 128) * DD];  // +128 rows: wmma overhang
__device__ __align__(16) float g_b0[NNODES * DD];
__device__ __align__(16) float g_b1[NNODES * DD];
__device__ int g_cnt[NNODES];      // zero at load; scan1 re-zeroes after reading
__device__ int g_ofs[NNODES];
__device__ int g_rowptr[NNODES + 1];
__device__ int g_pre[32];          // zeroed by layer-0 gemm each replay
__device__ int g_ssrc[NEDGES];
__device__ int g_perm[NNODES];
__device__ int g_dhist[512];       // zeroed by layer-0 gemm each replay
__device__ int g_dbase[512];

// ---------------------------------------------------------------------------
// Tensor-core GEMM: [128 nodes] x [128 cols] per block. 8 warps, each 64x32.
// Both xl (cols 0..63) and xr (64..127) use fp16 accumulators, direct store.
// Layer 0 (do_csr): zero g_pre/g_dhist + histogram dst into g_cnt.
// ---------------------------------------------------------------------------
__global__ __launch_bounds__(256) void k_gemm(const float* __restrict__ x,
                                              const float* __restrict__ Wl,
                                              const float* __restrict__ Wr,
                                              int n,
                                              const int* __restrict__ ei,
                                              int E, int do_csr) {
    extern __shared__ char smraw[];
    __half* xh = (__half*)smraw;                          // [128][XH_LD]
    __half* wh = (__half*)(smraw + 128 * XH_LD * 2);      // [64][W_LD]

    int tid = threadIdx.x;
    int nodeBase = blockIdx.x * 128;

    if (do_csr) {
        if (blockIdx.x == 0) {
            if (tid < 32) g_pre[tid] = 0;
            g_dhist[tid] = 0;
            g_dhist[tid + 256] = 0;
        }
        int stride = gridDim.x * blockDim.x;
        for (int e = blockIdx.x * blockDim.x + tid; e < E; e += stride)
            atomicAdd(&g_cnt[ei[E + e]], 1);
    }

    for (int g = tid; g < 2048; g += 256) {
        int row = g >> 4;
        int c4 = (g & 15) << 2;
        int gn = nodeBase + row;
        float4 v = (gn < n) ? *(const float4*)&x[(size_t)gn * DD + c4]
                            : make_float4(0.f, 0.f, 0.f, 0.f);
        __half2 h0 = __floats2half2_rn(v.x, v.y);
        __half2 h1 = __floats2half2_rn(v.z, v.w);
        uint2 pk;
        pk.x = *(unsigned*)&h0;
        pk.y = *(unsigned*)&h1;
        *(uint2*)&xh[row * XH_LD + c4] = pk;
    }
    for (int g = tid; g < 2048; g += 256) {
        int k = g >> 5;
        int c4 = (g & 31) << 2;
        float4 v = (c4 < 64) ? *(const float4*)&Wl[k * 64 + c4]
                             : *(const float4*)&Wr[k * 64 + (c4 - 64)];
        __half2 h0 = __floats2half2_rn(v.x, v.y);
        __half2 h1 = __floats2half2_rn(v.z, v.w);
        uint2 pk;
        pk.x = *(unsigned*)&h0;
        pk.y = *(unsigned*)&h1;
        *(uint2*)&wh[k * W_LD + c4] = pk;
    }
    __syncthreads();

    int warp = tid >> 5;
    int wr = warp >> 2;
    int wc = warp & 3;

    wmma::fragment<wmma::accumulator, 16, 16, 16, __half> cf[4][2];
#pragma unroll
    for (int i = 0; i < 4; i++)
#pragma unroll
        for (int j = 0; j < 2; j++)
            wmma::fill_fragment(cf[i][j], __float2half(0.f));

#pragma unroll
    for (int kk = 0; kk < 64; kk += 16) {
        wmma::fragment<wmma::matrix_a, 16, 16, 16, __half, wmma::row_major> af[4];
        wmma::fragment<wmma::matrix_b, 16, 16, 16, __half, wmma::row_major> bf[2];
#pragma unroll
        for (int i = 0; i < 4; i++)
            wmma::load_matrix_sync(af[i], &xh[(wr * 64 + i * 16) * XH_LD + kk], XH_LD);
#pragma unroll
        for (int j = 0; j < 2; j++)
            wmma::load_matrix_sync(bf[j], &wh[kk * W_LD + wc * 32 + j * 16], W_LD);
#pragma unroll
        for (int i = 0; i < 4; i++)
#pragma unroll
            for (int j = 0; j < 2; j++)
                wmma::mma_sync(cf[i][j], af[i], bf[j], cf[i][j]);
    }

    __half* dstBase = (wc < 2) ? g_xlh : g_xrh;
    int colBase = (wc < 2) ? wc * 32 : wc * 32 - 64;
#pragma unroll
    for (int i = 0; i < 4; i++) {
        int gr = nodeBase + wr * 64 + i * 16;
#pragma unroll
        for (int j = 0; j < 2; j++)
            wmma::store_matrix_sync(&dstBase[(size_t)gr * DD + colBase + j * 16],
                                    cf[i][j], DD, wmma::mem_row_major);
    }
}

// ------------------------- CSR build (once per launch) ----------------------
// scan1: prefix of g_cnt + SMEM degree histogram (one global add per bin/block).
__global__ __launch_bounds__(SCAN_BLK) void k_scan1(int n) {
    __shared__ int sh[SCAN_BLK];
    __shared__ int dh[512];
    int blk = blockIdx.x;
    int base = blk * SCAN_TILE + threadIdx.x * SCAN_ELEM;
    int t = threadIdx.x;
    dh[t] = 0;
    __syncthreads();

    int v[SCAN_ELEM];
    int sum = 0;
#pragma unroll
    for (int i = 0; i < SCAN_ELEM; i++) {
        int idx = base + i;
        v[i] = (idx < n) ? g_cnt[idx] : 0;
        if (idx < n) {
            g_cnt[idx] = 0;
            int bin = v[i] < 511 ? v[i] : 511;
            atomicAdd(&dh[bin], 1);              // smem atomic
        }
        sum += v[i];
    }
    sh[t] = sum;
    __syncthreads();
    for (int o = 1; o < SCAN_BLK; o <<= 1) {
        int x = (t >= o) ? sh[t - o] : 0;
        __syncthreads();
        sh[t] += x;
        __syncthreads();
    }
    int run = (t > 0) ? sh[t - 1] : 0;
    if (t == SCAN_BLK - 1) {
        int total = sh[SCAN_BLK - 1];
        for (int j = blk + 1; j < gridDim.x; j++) atomicAdd(&g_pre[j], total);
    }
#pragma unroll
    for (int i = 0; i < SCAN_ELEM; i++) {
        int idx = base + i;
        if (idx < n) { g_rowptr[idx] = run; g_ofs[idx] = run; }
        if (idx == n - 1) g_rowptr[n] = run + v[i];
        run += v[i];
    }
    // flush local degree histogram (one global atomic per nonzero bin)
    int c = dh[t];
    if (c) atomicAdd(&g_dhist[t], c);
}

__global__ __launch_bounds__(512) void k_degscan() {
    __shared__ int sh[512];
    int t = threadIdx.x;
    sh[t] = g_dhist[t];
    __syncthreads();
    for (int o = 1; o < 512; o <<= 1) {
        int x = (t >= o) ? sh[t - o] : 0;
        __syncthreads();
        sh[t] += x;
        __syncthreads();
    }
    g_dbase[t] = (t > 0) ? sh[t - 1] : 0;
}

// Block-aggregated degree scatter: one global atomic per bin per block
// reserves a contiguous range; in-block ranks via smem atomics.
__global__ __launch_bounds__(256) void k_degscatter(int n) {
    __shared__ int lh[512];     // local counts, then reused as running counters
    __shared__ int lbase[512];  // global base for this block's chunk per bin
    int t = threadIdx.x;
    lh[t] = 0; lh[t + 256] = 0;
    __syncthreads();

    int d = blockIdx.x * 256 + t;
    int bin = -1;
    if (d < n) {
        int deg = (g_rowptr[d + 1] + __ldg(&g_pre[(d + 1) >> 12]))
                - (g_rowptr[d] + __ldg(&g_pre[d >> 12]));
        bin = deg < 511 ? deg : 511;
        atomicAdd(&lh[bin], 1);  // smem
    }
    __syncthreads();

#pragma unroll
    for (int b = t; b < 512; b += 256) {
        int c = lh[b];
        lbase[b] = c ? atomicAdd(&g_dbase[b], c) : 0;
        lh[b] = 0;  // reset -> running counter
    }
    __syncthreads();

    if (d < n) {
        int r = atomicAdd(&lh[bin], 1);  // smem rank within block
        g_perm[lbase[bin] + r] = d;
    }
}

__global__ void k_scatter(const int* __restrict__ ei, int E) {
    int e = blockIdx.x * blockDim.x + threadIdx.x;
    if (e < E) {
        int d = ei[E + e];
        int pos = atomicAdd(&g_ofs[d], 1) + __ldg(&g_pre[d >> 12]);
        g_ssrc[pos] = ei[e];
    }
}

// ---------------------------------------------------------------------------
// Fused aggregation: half-warp per dst node (degree-sorted perm order),
// 4 ch/lane, packed fp16 edge math, fp32 den + epilogue.
// ---------------------------------------------------------------------------
__device__ __forceinline__ void edge_accum_h(int s, int j, unsigned mask16,
                                             __half2 xr01, __half2 xr23,
                                             __half2 a601, __half2 a623,
                                             __half2 a401, __half2 a423,
                                             __half2& acc01, __half2& acc23,
                                             float& den) {
    uint2 raw = *(const uint2*)&g_xlh[(size_t)s * DD + j];
    __half2 a01 = *(__half2*)&raw.x;
    __half2 a23 = *(__half2*)&raw.y;

    __half2 m01 = __hadd2(a01, xr01);
    __half2 m23 = __hadd2(a23, xr23);

    __half2 t = __hmul2(__habs2(m01), a401);
    t = __hfma2(m01, a601, t);
    t = __hfma2(__habs2(m23), a423, t);
    t = __hfma2(m23, a623, t);

    float2 pf = __half22float2(t);
    float part = pf.x + pf.y;
    part += __shfl_xor_sync(mask16, part, 1, 16);
    part += __shfl_xor_sync(mask16, part, 2, 16);

    float p = __expf(part);
    __half2 ph = __float2half2_rn(p);
    acc01 = __hfma2(ph, a01, acc01);
    acc23 = __hfma2(ph, a23, acc23);
    den += p;
}

__global__ __launch_bounds__(256) void k_agg(const float* __restrict__ xres,
                                             const float* __restrict__ att,
                                             const float* __restrict__ bias,
                                             const float* __restrict__ gamma,
                                             const float* __restrict__ beta,
                                             float* __restrict__ out, int n) {
    int warp = (blockIdx.x * blockDim.x + threadIdx.x) >> 5;
    int lane = threadIdx.x & 31;
    int hf = lane >> 4;
    int l16 = lane & 15;
    int slot = warp * 2 + hf;
    if (slot >= n) return;
    int d = g_perm[slot];
    unsigned mask16 = hf ? 0xFFFF0000u : 0x0000FFFFu;
    int j = l16 * 4;

    uint2 rawr = *(const uint2*)&g_xrh[(size_t)d * DD + j];
    __half2 xr01 = *(__half2*)&rawr.x;
    __half2 xr23 = *(__half2*)&rawr.y;

    float4 at4 = *(const float4*)(att + j);
    __half2 a601 = __floats2half2_rn(0.6f * at4.x, 0.6f * at4.y);
    __half2 a623 = __floats2half2_rn(0.6f * at4.z, 0.6f * at4.w);
    __half2 a401 = __floats2half2_rn(0.4f * at4.x, 0.4f * at4.y);
    __half2 a423 = __floats2half2_rn(0.4f * at4.z, 0.4f * at4.w);

    __half2 acc01 = __float2half2_rn(0.f);
    __half2 acc23 = __float2half2_rn(0.f);
    float den = 0.f;

    // self loop
    edge_accum_h(d, j, mask16, xr01, xr23, a601, a623, a401, a423,
                 acc01, acc23, den);

    int pre0 = __ldg(&g_pre[d >> 12]);
    int pre1 = __ldg(&g_pre[(d + 1) >> 12]);
    int begin = g_rowptr[d] + pre0;
    int end = g_rowptr[d + 1] + pre1;

    int svNext = (begin + l16 < end) ? g_ssrc[begin + l16] : 0;

    for (int base = begin; base < end; base += 16) {
        int sv = svNext;
        int nidx = base + 16 + l16;
        svNext = (nidx < end) ? g_ssrc[nidx] : 0;
        int cnt = end - base;
        if (cnt > 16) cnt = 16;
#pragma unroll 4
        for (int k = 0; k < cnt; k++) {
            int s = __shfl_sync(mask16, sv, k, 16);
            edge_accum_h(s, j, mask16, xr01, xr23, a601, a623, a401, a423,
                         acc01, acc23, den);
        }
    }

    // normalize + bias + residual (fp32 epilogue)
    float2 f01 = __half22float2(acc01);
    float2 f23 = __half22float2(acc23);
    float inv = 1.f / den;
    float4 xv = *(const float4*)&xres[(size_t)d * DD + j];
    float4 bi = *(const float4*)(bias + j);
    float v0 = f01.x * inv + bi.x + xv.x;
    float v1 = f01.y * inv + bi.y + xv.y;
    float v2 = f23.x * inv + bi.z + xv.z;
    float v3 = f23.y * inv + bi.w + xv.w;

    // LayerNorm over 64 ch (16-lane reduce)
    float s = v0 + v1 + v2 + v3;
    float s2 = v0 * v0 + v1 * v1 + v2 * v2 + v3 * v3;
#pragma unroll
    for (int o = 8; o; o >>= 1) {
        s += __shfl_xor_sync(mask16, s, o, 16);
        s2 += __shfl_xor_sync(mask16, s2, o, 16);
    }
    float mu = s * (1.f / 64.f);
    float var = s2 * (1.f / 64.f) - mu * mu;
    float rstd = rsqrtf(var + 1e-5f);

    float4 ga = *(const float4*)(gamma + j);
    float4 be = *(const float4*)(beta + j);
    float y0 = (v0 - mu) * rstd * ga.x + be.x;
    float y1 = (v1 - mu) * rstd * ga.y + be.y;
    float y2 = (v2 - mu) * rstd * ga.z + be.z;
    float y3 = (v3 - mu) * rstd * ga.w + be.w;

    const float ks = 0.70710678118654752f;
    y0 = 0.5f * y0 * (1.f + erff(y0 * ks));
    y1 = 0.5f * y1 * (1.f + erff(y1 * ks));
    y2 = 0.5f * y2 * (1.f + erff(y2 * ks));
    y3 = 0.5f * y3 * (1.f + erff(y3 * ks));

    *(float4*)&out[(size_t)d * DD + j] = make_float4(y0, y1, y2, y3);
}

// ---------------------------------------------------------------------------
extern "C" void kernel_launch(void* const* d_in, const int* in_sizes, int n_in,
                              void* d_out, int out_size) {
    const float* x = (const float*)d_in[0];
    const int* ei = (const int*)d_in[1];   // int32: [src(E), dst(E)]
    const float* Wl = (const float*)d_in[2];
    const float* Wr = (const float*)d_in[3];
    const float* att = (const float*)d_in[4];
    const float* bias = (const float*)d_in[5];
    const float* gamma = (const float*)d_in[6];
    const float* beta = (const float*)d_in[7];

    int n = in_sizes[0] / DD;
    int E = in_sizes[1] / 2;
    int Lnum = in_sizes[2] / (DD * DD);

    float *b0p = nullptr, *b1p = nullptr;
    cudaGetSymbolAddress((void**)&b0p, g_b0);
    cudaGetSymbolAddress((void**)&b1p, g_b1);

    const int gemmSmem = 128 * XH_LD * 2 + 64 * W_LD * 2;  // 35840

    static int attr_set = 0;
    if (!attr_set) {
        cudaFuncSetAttribute(k_gemm, cudaFuncAttributeMaxDynamicSharedMemorySize, gemmSmem);
        cudaFuncSetAttribute(k_agg, cudaFuncAttributePreferredSharedMemoryCarveout, 0);
        attr_set = 1;
    }

    int nbScan = (n + SCAN_TILE - 1) / SCAN_TILE;
    const float* cur = x;
    int aggBlocks = (n + 15) / 16;

    for (int i = 0; i < Lnum; i++) {
        k_gemm<<<(n + 127) / 128, 256, gemmSmem>>>(cur, Wl + (size_t)i * DD * DD,
                                                   Wr + (size_t)i * DD * DD, n,
                                                   ei, E, i == 0 ? 1 : 0);
        if (i == 0) {
            k_scan1<<<nbScan, SCAN_BLK>>>(n);
            k_degscan<<<1, 512>>>();
            k_degscatter<<<(n + 255) / 256, 256>>>(n);
            k_scatter<<<(E + 255) / 256, 256>>>(ei, E);
        }

        float* outp;
        if (i == Lnum - 1) outp = (float*)d_out;
        else outp = (i & 1) ? b1p : b0p;

        k_agg<<<aggBlocks, 256>>>(cur, att + (size_t)i * DD,
                                  bias + (size_t)i * DD,
                                  gamma + (size_t)i * DD,
                                  beta + (size_t)i * DD,
                                  outp, n);
        cur = outp;
    }
}

// round 15
// speedup vs baseline: 4.2603x; 1.1237x over previous
#include <cuda_runtime.h>
#include <cuda_fp16.h>
#include <mma.h>
#include <math.h>

using namespace nvcuda;

// GATv2 (L=3, H=4, C=16, D=64), N=100000, E=1280000 (+N self loops).
// R15 = R14 with agg widened: 8 lanes/node x 8 ch/lane (4 nodes/warp),
// one LDG.128 per edge, 1-shfl head reduce, segment (8-lane) masks everywhere.
// Degree-sorted perm keeps the 4 segments converged.

#define NNODES 100000
#define NEDGES 1280000
#define DD 64
#define XH_LD 72     // halves per row, x tile
#define W_LD 136     // halves per row, W tile
#define SCAN_BLK 512
#define SCAN_ELEM 8
#define SCAN_TILE (SCAN_BLK * SCAN_ELEM)  // 4096

__device__ __align__(128) __half g_xlh[(NNODES + 128) * DD];  // +128 rows: wmma overhang
__device__ __align__(128) __half g_xrh[(NNODES + 128) * DD];  // +128 rows: wmma overhang
__device__ __align__(16) float g_b0[NNODES * DD];
__device__ __align__(16) float g_b1[NNODES * DD];
__device__ int g_cnt[NNODES];      // zero at load; scan1 re-zeroes after reading
__device__ int g_ofs[NNODES];
__device__ int g_rowptr[NNODES + 1];
__device__ int g_pre[32];          // zeroed by layer-0 gemm each replay
__device__ int g_ssrc[NEDGES];
__device__ int g_perm[NNODES];
__device__ int g_dhist[512];       // zeroed by layer-0 gemm each replay
__device__ int g_dbase[512];

// ---------------------------------------------------------------------------
// Tensor-core GEMM (unchanged from R14).
// ---------------------------------------------------------------------------
__global__ __launch_bounds__(256) void k_gemm(const float* __restrict__ x,
                                              const float* __restrict__ Wl,
                                              const float* __restrict__ Wr,
                                              int n,
                                              const int* __restrict__ ei,
                                              int E, int do_csr) {
    extern __shared__ char smraw[];
    __half* xh = (__half*)smraw;                          // [128][XH_LD]
    __half* wh = (__half*)(smraw + 128 * XH_LD * 2);      // [64][W_LD]

    int tid = threadIdx.x;
    int nodeBase = blockIdx.x * 128;

    if (do_csr) {
        if (blockIdx.x == 0) {
            if (tid < 32) g_pre[tid] = 0;
            g_dhist[tid] = 0;
            g_dhist[tid + 256] = 0;
        }
        int stride = gridDim.x * blockDim.x;
        for (int e = blockIdx.x * blockDim.x + tid; e < E; e += stride)
            atomicAdd(&g_cnt[ei[E + e]], 1);
    }

    for (int g = tid; g < 2048; g += 256) {
        int row = g >> 4;
        int c4 = (g & 15) << 2;
        int gn = nodeBase + row;
        float4 v = (gn < n) ? *(const float4*)&x[(size_t)gn * DD + c4]
                            : make_float4(0.f, 0.f, 0.f, 0.f);
        __half2 h0 = __floats2half2_rn(v.x, v.y);
        __half2 h1 = __floats2half2_rn(v.z, v.w);
        uint2 pk;
        pk.x = *(unsigned*)&h0;
        pk.y = *(unsigned*)&h1;
        *(uint2*)&xh[row * XH_LD + c4] = pk;
    }
    for (int g = tid; g < 2048; g += 256) {
        int k = g >> 5;
        int c4 = (g & 31) << 2;
        float4 v = (c4 < 64) ? *(const float4*)&Wl[k * 64 + c4]
                             : *(const float4*)&Wr[k * 64 + (c4 - 64)];
        __half2 h0 = __floats2half2_rn(v.x, v.y);
        __half2 h1 = __floats2half2_rn(v.z, v.w);
        uint2 pk;
        pk.x = *(unsigned*)&h0;
        pk.y = *(unsigned*)&h1;
        *(uint2*)&wh[k * W_LD + c4] = pk;
    }
    __syncthreads();

    int warp = tid >> 5;
    int wr = warp >> 2;
    int wc = warp & 3;

    wmma::fragment<wmma::accumulator, 16, 16, 16, __half> cf[4][2];
#pragma unroll
    for (int i = 0; i < 4; i++)
#pragma unroll
        for (int j = 0; j < 2; j++)
            wmma::fill_fragment(cf[i][j], __float2half(0.f));

#pragma unroll
    for (int kk = 0; kk < 64; kk += 16) {
        wmma::fragment<wmma::matrix_a, 16, 16, 16, __half, wmma::row_major> af[4];
        wmma::fragment<wmma::matrix_b, 16, 16, 16, __half, wmma::row_major> bf[2];
#pragma unroll
        for (int i = 0; i < 4; i++)
            wmma::load_matrix_sync(af[i], &xh[(wr * 64 + i * 16) * XH_LD + kk], XH_LD);
#pragma unroll
        for (int j = 0; j < 2; j++)
            wmma::load_matrix_sync(bf[j], &wh[kk * W_LD + wc * 32 + j * 16], W_LD);
#pragma unroll
        for (int i = 0; i < 4; i++)
#pragma unroll
            for (int j = 0; j < 2; j++)
                wmma::mma_sync(cf[i][j], af[i], bf[j], cf[i][j]);
    }

    __half* dstBase = (wc < 2) ? g_xlh : g_xrh;
    int colBase = (wc < 2) ? wc * 32 : wc * 32 - 64;
#pragma unroll
    for (int i = 0; i < 4; i++) {
        int gr = nodeBase + wr * 64 + i * 16;
#pragma unroll
        for (int j = 0; j < 2; j++)
            wmma::store_matrix_sync(&dstBase[(size_t)gr * DD + colBase + j * 16],
                                    cf[i][j], DD, wmma::mem_row_major);
    }
}

// ------------------------- CSR build (once per launch) ----------------------
__global__ __launch_bounds__(SCAN_BLK) void k_scan1(int n) {
    __shared__ int sh[SCAN_BLK];
    __shared__ int dh[512];
    int blk = blockIdx.x;
    int base = blk * SCAN_TILE + threadIdx.x * SCAN_ELEM;
    int t = threadIdx.x;
    dh[t] = 0;
    __syncthreads();

    int v[SCAN_ELEM];
    int sum = 0;
#pragma unroll
    for (int i = 0; i < SCAN_ELEM; i++) {
        int idx = base + i;
        v[i] = (idx < n) ? g_cnt[idx] : 0;
        if (idx < n) {
            g_cnt[idx] = 0;
            int bin = v[i] < 511 ? v[i] : 511;
            atomicAdd(&dh[bin], 1);
        }
        sum += v[i];
    }
    sh[t] = sum;
    __syncthreads();
    for (int o = 1; o < SCAN_BLK; o <<= 1) {
        int x = (t >= o) ? sh[t - o] : 0;
        __syncthreads();
        sh[t] += x;
        __syncthreads();
    }
    int run = (t > 0) ? sh[t - 1] : 0;
    if (t == SCAN_BLK - 1) {
        int total = sh[SCAN_BLK - 1];
        for (int j = blk + 1; j < gridDim.x; j++) atomicAdd(&g_pre[j], total);
    }
#pragma unroll
    for (int i = 0; i < SCAN_ELEM; i++) {
        int idx = base + i;
        if (idx < n) { g_rowptr[idx] = run; g_ofs[idx] = run; }
        if (idx == n - 1) g_rowptr[n] = run + v[i];
        run += v[i];
    }
    int c = dh[t];
    if (c) atomicAdd(&g_dhist[t], c);
}

__global__ __launch_bounds__(512) void k_degscan() {
    __shared__ int sh[512];
    int t = threadIdx.x;
    sh[t] = g_dhist[t];
    __syncthreads();
    for (int o = 1; o < 512; o <<= 1) {
        int x = (t >= o) ? sh[t - o] : 0;
        __syncthreads();
        sh[t] += x;
        __syncthreads();
    }
    g_dbase[t] = (t > 0) ? sh[t - 1] : 0;
}

__global__ __launch_bounds__(256) void k_degscatter(int n) {
    __shared__ int lh[512];
    __shared__ int lbase[512];
    int t = threadIdx.x;
    lh[t] = 0; lh[t + 256] = 0;
    __syncthreads();

    int d = blockIdx.x * 256 + t;
    int bin = -1;
    if (d < n) {
        int deg = (g_rowptr[d + 1] + __ldg(&g_pre[(d + 1) >> 12]))
                - (g_rowptr[d] + __ldg(&g_pre[d >> 12]));
        bin = deg < 511 ? deg : 511;
        atomicAdd(&lh[bin], 1);
    }
    __syncthreads();

#pragma unroll
    for (int b = t; b < 512; b += 256) {
        int c = lh[b];
        lbase[b] = c ? atomicAdd(&g_dbase[b], c) : 0;
        lh[b] = 0;
    }
    __syncthreads();

    if (d < n) {
        int r = atomicAdd(&lh[bin], 1);
        g_perm[lbase[bin] + r] = d;
    }
}

__global__ void k_scatter(const int* __restrict__ ei, int E) {
    int e = blockIdx.x * blockDim.x + threadIdx.x;
    if (e < E) {
        int d = ei[E + e];
        int pos = atomicAdd(&g_ofs[d], 1) + __ldg(&g_pre[d >> 12]);
        g_ssrc[pos] = ei[e];
    }
}

// ---------------------------------------------------------------------------
// Fused aggregation: 8 lanes/node, 8 ch/lane, 4 nodes/warp (degree-sorted).
// One LDG.128 per edge, 1-shfl head reduce, 8-lane segment masks.
// ---------------------------------------------------------------------------
__device__ __forceinline__ void edge_accum8(int s, int j, unsigned m8,
                                            const __half2 xr[4],
                                            const __half2 a6[4],
                                            const __half2 a4[4],
                                            __half2 acc[4], float& den) {
    uint4 raw = *(const uint4*)&g_xlh[(size_t)s * DD + j];
    __half2 a0 = *(__half2*)&raw.x;
    __half2 a1 = *(__half2*)&raw.y;
    __half2 a2 = *(__half2*)&raw.z;
    __half2 a3 = *(__half2*)&raw.w;

    __half2 m0 = __hadd2(a0, xr[0]);
    __half2 m1 = __hadd2(a1, xr[1]);
    __half2 m2 = __hadd2(a2, xr[2]);
    __half2 m3 = __hadd2(a3, xr[3]);

    __half2 t = __hmul2(__habs2(m0), a4[0]);
    t = __hfma2(m0, a6[0], t);
    t = __hfma2(__habs2(m1), a4[1], t);
    t = __hfma2(m1, a6[1], t);
    t = __hfma2(__habs2(m2), a4[2], t);
    t = __hfma2(m2, a6[2], t);
    t = __hfma2(__habs2(m3), a4[3], t);
    t = __hfma2(m3, a6[3], t);

    float2 pf = __half22float2(t);
    float part = pf.x + pf.y;
    part += __shfl_xor_sync(m8, part, 1, 8);   // head = 16 ch = 2 lanes

    float p = __expf(part);
    __half2 ph = __float2half2_rn(p);
    acc[0] = __hfma2(ph, a0, acc[0]);
    acc[1] = __hfma2(ph, a1, acc[1]);
    acc[2] = __hfma2(ph, a2, acc[2]);
    acc[3] = __hfma2(ph, a3, acc[3]);
    den += p;
}

__global__ __launch_bounds__(256) void k_agg(const float* __restrict__ xres,
                                             const float* __restrict__ att,
                                             const float* __restrict__ bias,
                                             const float* __restrict__ gamma,
                                             const float* __restrict__ beta,
                                             float* __restrict__ out, int n) {
    int warp = (blockIdx.x * blockDim.x + threadIdx.x) >> 5;
    int lane = threadIdx.x & 31;
    int seg = lane >> 3;       // node within warp (0..3)
    int l8 = lane & 7;         // channel lane (8 ch each)
    int slot = warp * 4 + seg;
    if (slot >= n) return;
    int d = g_perm[slot];
    unsigned m8 = 0xFFu << (seg * 8);
    int j = l8 * 8;

    __half2 xr[4], a6[4], a4[4];
    {
        uint4 rawr = *(const uint4*)&g_xrh[(size_t)d * DD + j];
        xr[0] = *(__half2*)&rawr.x;
        xr[1] = *(__half2*)&rawr.y;
        xr[2] = *(__half2*)&rawr.z;
        xr[3] = *(__half2*)&rawr.w;
        float4 u0 = *(const float4*)(att + j);
        float4 u1 = *(const float4*)(att + j + 4);
        a6[0] = __floats2half2_rn(0.6f * u0.x, 0.6f * u0.y);
        a6[1] = __floats2half2_rn(0.6f * u0.z, 0.6f * u0.w);
        a6[2] = __floats2half2_rn(0.6f * u1.x, 0.6f * u1.y);
        a6[3] = __floats2half2_rn(0.6f * u1.z, 0.6f * u1.w);
        a4[0] = __floats2half2_rn(0.4f * u0.x, 0.4f * u0.y);
        a4[1] = __floats2half2_rn(0.4f * u0.z, 0.4f * u0.w);
        a4[2] = __floats2half2_rn(0.4f * u1.x, 0.4f * u1.y);
        a4[3] = __floats2half2_rn(0.4f * u1.z, 0.4f * u1.w);
    }

    __half2 acc[4];
    acc[0] = acc[1] = acc[2] = acc[3] = __float2half2_rn(0.f);
    float den = 0.f;

    // self loop
    edge_accum8(d, j, m8, xr, a6, a4, acc, den);

    int pre0 = __ldg(&g_pre[d >> 12]);
    int pre1 = __ldg(&g_pre[(d + 1) >> 12]);
    int begin = g_rowptr[d] + pre0;
    int end = g_rowptr[d + 1] + pre1;

    int svNext = (begin + l8 < end) ? g_ssrc[begin + l8] : 0;

    for (int base = begin; base < end; base += 8) {
        int sv = svNext;
        int nidx = base + 8 + l8;
        svNext = (nidx < end) ? g_ssrc[nidx] : 0;
        int cnt = end - base;
        if (cnt > 8) cnt = 8;
#pragma unroll 4
        for (int k = 0; k < cnt; k++) {
            int s = __shfl_sync(m8, sv, k, 8);
            edge_accum8(s, j, m8, xr, a6, a4, acc, den);
        }
    }

    // normalize + bias + residual (fp32 epilogue)
    float inv = 1.f / den;
    float v[8];
    {
        float2 f0 = __half22float2(acc[0]);
        float2 f1 = __half22float2(acc[1]);
        float2 f2 = __half22float2(acc[2]);
        float2 f3 = __half22float2(acc[3]);
        float fa[8] = {f0.x, f0.y, f1.x, f1.y, f2.x, f2.y, f3.x, f3.y};
        float4 x0 = *(const float4*)&xres[(size_t)d * DD + j];
        float4 x1 = *(const float4*)&xres[(size_t)d * DD + j + 4];
        float4 b0 = *(const float4*)(bias + j);
        float4 b1 = *(const float4*)(bias + j + 4);
        float xv[8] = {x0.x, x0.y, x0.z, x0.w, x1.x, x1.y, x1.z, x1.w};
        float bi[8] = {b0.x, b0.y, b0.z, b0.w, b1.x, b1.y, b1.z, b1.w};
#pragma unroll
        for (int c = 0; c < 8; c++) v[c] = fa[c] * inv + bi[c] + xv[c];
    }

    // LayerNorm over 64 ch (8-lane segment reduce)
    float s = 0.f, s2 = 0.f;
#pragma unroll
    for (int c = 0; c < 8; c++) { s += v[c]; s2 += v[c] * v[c]; }
#pragma unroll
    for (int o = 4; o; o >>= 1) {
        s += __shfl_xor_sync(m8, s, o, 8);
        s2 += __shfl_xor_sync(m8, s2, o, 8);
    }
    float mu = s * (1.f / 64.f);
    float var = s2 * (1.f / 64.f) - mu * mu;
    float rstd = rsqrtf(var + 1e-5f);

    float4 g0 = *(const float4*)(gamma + j);
    float4 g1 = *(const float4*)(gamma + j + 4);
    float4 e0 = *(const float4*)(beta + j);
    float4 e1 = *(const float4*)(beta + j + 4);
    float ga[8] = {g0.x, g0.y, g0.z, g0.w, g1.x, g1.y, g1.z, g1.w};
    float be[8] = {e0.x, e0.y, e0.z, e0.w, e1.x, e1.y, e1.z, e1.w};

    const float ks = 0.70710678118654752f;
    float y[8];
#pragma unroll
    for (int c = 0; c < 8; c++) {
        float t = (v[c] - mu) * rstd * ga[c] + be[c];
        y[c] = 0.5f * t * (1.f + erff(t * ks));
    }

    *(float4*)&out[(size_t)d * DD + j] = make_float4(y[0], y[1], y[2], y[3]);
    *(float4*)&out[(size_t)d * DD + j + 4] = make_float4(y[4], y[5], y[6], y[7]);
}

// ---------------------------------------------------------------------------
extern "C" void kernel_launch(void* const* d_in, const int* in_sizes, int n_in,
                              void* d_out, int out_size) {
    const float* x = (const float*)d_in[0];
    const int* ei = (const int*)d_in[1];   // int32: [src(E), dst(E)]
    const float* Wl = (const float*)d_in[2];
    const float* Wr = (const float*)d_in[3];
    const float* att = (const float*)d_in[4];
    const float* bias = (const float*)d_in[5];
    const float* gamma = (const float*)d_in[6];
    const float* beta = (const float*)d_in[7];

    int n = in_sizes[0] / DD;
    int E = in_sizes[1] / 2;
    int Lnum = in_sizes[2] / (DD * DD);

    float *b0p = nullptr, *b1p = nullptr;
    cudaGetSymbolAddress((void**)&b0p, g_b0);
    cudaGetSymbolAddress((void**)&b1p, g_b1);

    const int gemmSmem = 128 * XH_LD * 2 + 64 * W_LD * 2;  // 35840

    static int attr_set = 0;
    if (!attr_set) {
        cudaFuncSetAttribute(k_gemm, cudaFuncAttributeMaxDynamicSharedMemorySize, gemmSmem);
        cudaFuncSetAttribute(k_agg, cudaFuncAttributePreferredSharedMemoryCarveout, 0);
        attr_set = 1;
    }

    int nbScan = (n + SCAN_TILE - 1) / SCAN_TILE;
    const float* cur = x;
    int aggBlocks = (n + 31) / 32;  // 32 nodes per 256-thread block

    for (int i = 0; i < Lnum; i++) {
        k_gemm<<<(n + 127) / 128, 256, gemmSmem>>>(cur, Wl + (size_t)i * DD * DD,
                                                   Wr + (size_t)i * DD * DD, n,
                                                   ei, E, i == 0 ? 1 : 0);
        if (i == 0) {
            k_scan1<<<nbScan, SCAN_BLK>>>(n);
            k_degscan<<<1, 512>>>();
            k_degscatter<<<(n + 255) / 256, 256>>>(n);
            k_scatter<<<(E + 255) / 256, 256>>>(ei, E);
        }

        float* outp;
        if (i == Lnum - 1) outp = (float*)d_out;
        else outp = (i & 1) ? b1p : b0p;

        k_agg<<<aggBlocks, 256>>>(cur, att + (size_t)i * DD,
                                  bias + (size_t)i * DD,
                                  gamma + (size_t)i * DD,
                                  beta + (size_t)i * DD,
                                  outp, n);
        cur = outp;
    }
}

// round 16
// speedup vs baseline: 4.4179x; 1.0370x over previous
#include <cuda_runtime.h>
#include <cuda_fp16.h>
#include <mma.h>
#include <math.h>

using namespace nvcuda;

// GATv2 (L=3, H=4, C=16, D=64), N=100000, E=1280000 (+N self loops).
// R16 = R15 with:
//  - CSR build (hist, scan1, degscan, degscatter, scatter) on a second stream,
//    fork-join overlapped with layer-0 gemm (streams/events created on first,
//    uncaptured, call; fork-join event pattern is graph-capturable).
//  - gemm blocks shrunk to 64 nodes x 128 cols (26.6KB smem, 2x2 frags/warp)
//    for ~4 CTAs/SM instead of 2 -> latency hiding.
//  - agg unchanged (R15: 8 lanes/node, 8 ch/lane, degree-sorted perm).

#define NNODES 100000
#define NEDGES 1280000
#define DD 64
#define XH_LD 72     // halves per row, x tile
#define W_LD 136     // halves per row, W tile
#define SCAN_BLK 512
#define SCAN_ELEM 8
#define SCAN_TILE (SCAN_BLK * SCAN_ELEM)  // 4096

__device__ __align__(128) __half g_xlh[(NNODES + 128) * DD];
__device__ __align__(128) __half g_xrh[(NNODES + 128) * DD];
__device__ __align__(16) float g_b0[NNODES * DD];
__device__ __align__(16) float g_b1[NNODES * DD];
__device__ int g_cnt[NNODES];      // zero at load; scan1 re-zeroes after reading
__device__ int g_ofs[NNODES];
__device__ int g_rowptr[NNODES + 1];
__device__ int g_pre[32];          // zeroed by k_hist each replay
__device__ int g_ssrc[NEDGES];
__device__ int g_perm[NNODES];
__device__ int g_dhist[512];       // zeroed by k_hist each replay
__device__ int g_dbase[512];

// ---------------------------------------------------------------------------
// Tensor-core GEMM: [64 nodes] x [128 cols] per block, 8 warps, 32x32/warp.
// cols 0..63 -> xl, 64..127 -> xr (both fp16 acc, direct store).
// ---------------------------------------------------------------------------
__global__ __launch_bounds__(256) void k_gemm(const float* __restrict__ x,
                                              const float* __restrict__ Wl,
                                              const float* __restrict__ Wr,
                                              int n) {
    extern __shared__ char smraw[];
    __half* xh = (__half*)smraw;                          // [64][XH_LD]
    __half* wh = (__half*)(smraw + 64 * XH_LD * 2);       // [64][W_LD]

    int tid = threadIdx.x;
    int nodeBase = blockIdx.x * 64;

    // x tile: 64 nodes x 64 ch -> fp16 smem (zero-pad past n)
    for (int g = tid; g < 1024; g += 256) {
        int row = g >> 4;
        int c4 = (g & 15) << 2;
        int gn = nodeBase + row;
        float4 v = (gn < n) ? *(const float4*)&x[(size_t)gn * DD + c4]
                            : make_float4(0.f, 0.f, 0.f, 0.f);
        __half2 h0 = __floats2half2_rn(v.x, v.y);
        __half2 h1 = __floats2half2_rn(v.z, v.w);
        uint2 pk;
        pk.x = *(unsigned*)&h0;
        pk.y = *(unsigned*)&h1;
        *(uint2*)&xh[row * XH_LD + c4] = pk;
    }
    // W: wh[k][col], col 0..63 Wl, 64..127 Wr
    for (int g = tid; g < 2048; g += 256) {
        int k = g >> 5;
        int c4 = (g & 31) << 2;
        float4 v = (c4 < 64) ? *(const float4*)&Wl[k * 64 + c4]
                             : *(const float4*)&Wr[k * 64 + (c4 - 64)];
        __half2 h0 = __floats2half2_rn(v.x, v.y);
        __half2 h1 = __floats2half2_rn(v.z, v.w);
        uint2 pk;
        pk.x = *(unsigned*)&h0;
        pk.y = *(unsigned*)&h1;
        *(uint2*)&wh[k * W_LD + c4] = pk;
    }
    __syncthreads();

    int warp = tid >> 5;
    int wr = warp >> 2;        // 0..1 : 32-row block
    int wc = warp & 3;         // 0..3 : 32-col block

    wmma::fragment<wmma::accumulator, 16, 16, 16, __half> cf[2][2];
#pragma unroll
    for (int i = 0; i < 2; i++)
#pragma unroll
        for (int j = 0; j < 2; j++)
            wmma::fill_fragment(cf[i][j], __float2half(0.f));

#pragma unroll
    for (int kk = 0; kk < 64; kk += 16) {
        wmma::fragment<wmma::matrix_a, 16, 16, 16, __half, wmma::row_major> af[2];
        wmma::fragment<wmma::matrix_b, 16, 16, 16, __half, wmma::row_major> bf[2];
#pragma unroll
        for (int i = 0; i < 2; i++)
            wmma::load_matrix_sync(af[i], &xh[(wr * 32 + i * 16) * XH_LD + kk], XH_LD);
#pragma unroll
        for (int j = 0; j < 2; j++)
            wmma::load_matrix_sync(bf[j], &wh[kk * W_LD + wc * 32 + j * 16], W_LD);
#pragma unroll
        for (int i = 0; i < 2; i++)
#pragma unroll
            for (int j = 0; j < 2; j++)
                wmma::mma_sync(cf[i][j], af[i], bf[j], cf[i][j]);
    }

    __half* dstBase = (wc < 2) ? g_xlh : g_xrh;
    int colBase = (wc < 2) ? wc * 32 : wc * 32 - 64;
#pragma unroll
    for (int i = 0; i < 2; i++) {
        int gr = nodeBase + wr * 32 + i * 16;
#pragma unroll
        for (int j = 0; j < 2; j++)
            wmma::store_matrix_sync(&dstBase[(size_t)gr * DD + colBase + j * 16],
                                    cf[i][j], DD, wmma::mem_row_major);
    }
}

// ------------------------- CSR build (second stream) ------------------------
__global__ void k_hist(const int* __restrict__ ei, int E) {
    int e = blockIdx.x * blockDim.x + threadIdx.x;
    if (blockIdx.x == 0) {
        if (threadIdx.x < 32) g_pre[threadIdx.x] = 0;
        if (threadIdx.x < 256) { g_dhist[threadIdx.x] = 0; g_dhist[threadIdx.x + 256] = 0; }
    }
    if (e < E) atomicAdd(&g_cnt[ei[E + e]], 1);
}

__global__ __launch_bounds__(SCAN_BLK) void k_scan1(int n) {
    __shared__ int sh[SCAN_BLK];
    __shared__ int dh[512];
    int blk = blockIdx.x;
    int base = blk * SCAN_TILE + threadIdx.x * SCAN_ELEM;
    int t = threadIdx.x;
    dh[t] = 0;
    __syncthreads();

    int v[SCAN_ELEM];
    int sum = 0;
#pragma unroll
    for (int i = 0; i < SCAN_ELEM; i++) {
        int idx = base + i;
        v[i] = (idx < n) ? g_cnt[idx] : 0;
        if (idx < n) {
            g_cnt[idx] = 0;
            int bin = v[i] < 511 ? v[i] : 511;
            atomicAdd(&dh[bin], 1);
        }
        sum += v[i];
    }
    sh[t] = sum;
    __syncthreads();
    for (int o = 1; o < SCAN_BLK; o <<= 1) {
        int x = (t >= o) ? sh[t - o] : 0;
        __syncthreads();
        sh[t] += x;
        __syncthreads();
    }
    int run = (t > 0) ? sh[t - 1] : 0;
    if (t == SCAN_BLK - 1) {
        int total = sh[SCAN_BLK - 1];
        for (int j = blk + 1; j < gridDim.x; j++) atomicAdd(&g_pre[j], total);
    }
#pragma unroll
    for (int i = 0; i < SCAN_ELEM; i++) {
        int idx = base + i;
        if (idx < n) { g_rowptr[idx] = run; g_ofs[idx] = run; }
        if (idx == n - 1) g_rowptr[n] = run + v[i];
        run += v[i];
    }
    int c = dh[t];
    if (c) atomicAdd(&g_dhist[t], c);
}

__global__ __launch_bounds__(512) void k_degscan() {
    __shared__ int sh[512];
    int t = threadIdx.x;
    sh[t] = g_dhist[t];
    __syncthreads();
    for (int o = 1; o < 512; o <<= 1) {
        int x = (t >= o) ? sh[t - o] : 0;
        __syncthreads();
        sh[t] += x;
        __syncthreads();
    }
    g_dbase[t] = (t > 0) ? sh[t - 1] : 0;
}

__global__ __launch_bounds__(256) void k_degscatter(int n) {
    __shared__ int lh[512];
    __shared__ int lbase[512];
    int t = threadIdx.x;
    lh[t] = 0; lh[t + 256] = 0;
    __syncthreads();

    int d = blockIdx.x * 256 + t;
    int bin = -1;
    if (d < n) {
        int deg = (g_rowptr[d + 1] + __ldg(&g_pre[(d + 1) >> 12]))
                - (g_rowptr[d] + __ldg(&g_pre[d >> 12]));
        bin = deg < 511 ? deg : 511;
        atomicAdd(&lh[bin], 1);
    }
    __syncthreads();

#pragma unroll
    for (int b = t; b < 512; b += 256) {
        int c = lh[b];
        lbase[b] = c ? atomicAdd(&g_dbase[b], c) : 0;
        lh[b] = 0;
    }
    __syncthreads();

    if (d < n) {
        int r = atomicAdd(&lh[bin], 1);
        g_perm[lbase[bin] + r] = d;
    }
}

__global__ void k_scatter(const int* __restrict__ ei, int E) {
    int e = blockIdx.x * blockDim.x + threadIdx.x;
    if (e < E) {
        int d = ei[E + e];
        int pos = atomicAdd(&g_ofs[d], 1) + __ldg(&g_pre[d >> 12]);
        g_ssrc[pos] = ei[e];
    }
}

// ---------------------------------------------------------------------------
// Fused aggregation (unchanged R15): 8 lanes/node, 8 ch/lane, 4 nodes/warp.
// ---------------------------------------------------------------------------
__device__ __forceinline__ void edge_accum8(int s, int j, unsigned m8,
                                            const __half2 xr[4],
                                            const __half2 a6[4],
                                            const __half2 a4[4],
                                            __half2 acc[4], float& den) {
    uint4 raw = *(const uint4*)&g_xlh[(size_t)s * DD + j];
    __half2 a0 = *(__half2*)&raw.x;
    __half2 a1 = *(__half2*)&raw.y;
    __half2 a2 = *(__half2*)&raw.z;
    __half2 a3 = *(__half2*)&raw.w;

    __half2 m0 = __hadd2(a0, xr[0]);
    __half2 m1 = __hadd2(a1, xr[1]);
    __half2 m2 = __hadd2(a2, xr[2]);
    __half2 m3 = __hadd2(a3, xr[3]);

    __half2 t = __hmul2(__habs2(m0), a4[0]);
    t = __hfma2(m0, a6[0], t);
    t = __hfma2(__habs2(m1), a4[1], t);
    t = __hfma2(m1, a6[1], t);
    t = __hfma2(__habs2(m2), a4[2], t);
    t = __hfma2(m2, a6[2], t);
    t = __hfma2(__habs2(m3), a4[3], t);
    t = __hfma2(m3, a6[3], t);

    float2 pf = __half22float2(t);
    float part = pf.x + pf.y;
    part += __shfl_xor_sync(m8, part, 1, 8);

    float p = __expf(part);
    __half2 ph = __float2half2_rn(p);
    acc[0] = __hfma2(ph, a0, acc[0]);
    acc[1] = __hfma2(ph, a1, acc[1]);
    acc[2] = __hfma2(ph, a2, acc[2]);
    acc[3] = __hfma2(ph, a3, acc[3]);
    den += p;
}

__global__ __launch_bounds__(256) void k_agg(const float* __restrict__ xres,
                                             const float* __restrict__ att,
                                             const float* __restrict__ bias,
                                             const float* __restrict__ gamma,
                                             const float* __restrict__ beta,
                                             float* __restrict__ out, int n) {
    int warp = (blockIdx.x * blockDim.x + threadIdx.x) >> 5;
    int lane = threadIdx.x & 31;
    int seg = lane >> 3;
    int l8 = lane & 7;
    int slot = warp * 4 + seg;
    if (slot >= n) return;
    int d = g_perm[slot];
    unsigned m8 = 0xFFu << (seg * 8);
    int j = l8 * 8;

    __half2 xr[4], a6[4], a4[4];
    {
        uint4 rawr = *(const uint4*)&g_xrh[(size_t)d * DD + j];
        xr[0] = *(__half2*)&rawr.x;
        xr[1] = *(__half2*)&rawr.y;
        xr[2] = *(__half2*)&rawr.z;
        xr[3] = *(__half2*)&rawr.w;
        float4 u0 = *(const float4*)(att + j);
        float4 u1 = *(const float4*)(att + j + 4);
        a6[0] = __floats2half2_rn(0.6f * u0.x, 0.6f * u0.y);
        a6[1] = __floats2half2_rn(0.6f * u0.z, 0.6f * u0.w);
        a6[2] = __floats2half2_rn(0.6f * u1.x, 0.6f * u1.y);
        a6[3] = __floats2half2_rn(0.6f * u1.z, 0.6f * u1.w);
        a4[0] = __floats2half2_rn(0.4f * u0.x, 0.4f * u0.y);
        a4[1] = __floats2half2_rn(0.4f * u0.z, 0.4f * u0.w);
        a4[2] = __floats2half2_rn(0.4f * u1.x, 0.4f * u1.y);
        a4[3] = __floats2half2_rn(0.4f * u1.z, 0.4f * u1.w);
    }

    __half2 acc[4];
    acc[0] = acc[1] = acc[2] = acc[3] = __float2half2_rn(0.f);
    float den = 0.f;

    // self loop
    edge_accum8(d, j, m8, xr, a6, a4, acc, den);

    int pre0 = __ldg(&g_pre[d >> 12]);
    int pre1 = __ldg(&g_pre[(d + 1) >> 12]);
    int begin = g_rowptr[d] + pre0;
    int end = g_rowptr[d + 1] + pre1;

    int svNext = (begin + l8 < end) ? g_ssrc[begin + l8] : 0;

    for (int base = begin; base < end; base += 8) {
        int sv = svNext;
        int nidx = base + 8 + l8;
        svNext = (nidx < end) ? g_ssrc[nidx] : 0;
        int cnt = end - base;
        if (cnt > 8) cnt = 8;
#pragma unroll 4
        for (int k = 0; k < cnt; k++) {
            int s = __shfl_sync(m8, sv, k, 8);
            edge_accum8(s, j, m8, xr, a6, a4, acc, den);
        }
    }

    // normalize + bias + residual (fp32 epilogue)
    float inv = 1.f / den;
    float v[8];
    {
        float2 f0 = __half22float2(acc[0]);
        float2 f1 = __half22float2(acc[1]);
        float2 f2 = __half22float2(acc[2]);
        float2 f3 = __half22float2(acc[3]);
        float fa[8] = {f0.x, f0.y, f1.x, f1.y, f2.x, f2.y, f3.x, f3.y};
        float4 x0 = *(const float4*)&xres[(size_t)d * DD + j];
        float4 x1 = *(const float4*)&xres[(size_t)d * DD + j + 4];
        float4 b0 = *(const float4*)(bias + j);
        float4 b1 = *(const float4*)(bias + j + 4);
        float xv[8] = {x0.x, x0.y, x0.z, x0.w, x1.x, x1.y, x1.z, x1.w};
        float bi[8] = {b0.x, b0.y, b0.z, b0.w, b1.x, b1.y, b1.z, b1.w};
#pragma unroll
        for (int c = 0; c < 8; c++) v[c] = fa[c] * inv + bi[c] + xv[c];
    }

    // LayerNorm over 64 ch (8-lane segment reduce)
    float s = 0.f, s2 = 0.f;
#pragma unroll
    for (int c = 0; c < 8; c++) { s += v[c]; s2 += v[c] * v[c]; }
#pragma unroll
    for (int o = 4; o; o >>= 1) {
        s += __shfl_xor_sync(m8, s, o, 8);
        s2 += __shfl_xor_sync(m8, s2, o, 8);
    }
    float mu = s * (1.f / 64.f);
    float var = s2 * (1.f / 64.f) - mu * mu;
    float rstd = rsqrtf(var + 1e-5f);

    float4 g0 = *(const float4*)(gamma + j);
    float4 g1 = *(const float4*)(gamma + j + 4);
    float4 e0 = *(const float4*)(beta + j);
    float4 e1 = *(const float4*)(beta + j + 4);
    float ga[8] = {g0.x, g0.y, g0.z, g0.w, g1.x, g1.y, g1.z, g1.w};
    float be[8] = {e0.x, e0.y, e0.z, e0.w, e1.x, e1.y, e1.z, e1.w};

    const float ks = 0.70710678118654752f;
    float y[8];
#pragma unroll
    for (int c = 0; c < 8; c++) {
        float t = (v[c] - mu) * rstd * ga[c] + be[c];
        y[c] = 0.5f * t * (1.f + erff(t * ks));
    }

    *(float4*)&out[(size_t)d * DD + j] = make_float4(y[0], y[1], y[2], y[3]);
    *(float4*)&out[(size_t)d * DD + j + 4] = make_float4(y[4], y[5], y[6], y[7]);
}

// ---------------------------------------------------------------------------
extern "C" void kernel_launch(void* const* d_in, const int* in_sizes, int n_in,
                              void* d_out, int out_size) {
    const float* x = (const float*)d_in[0];
    const int* ei = (const int*)d_in[1];   // int32: [src(E), dst(E)]
    const float* Wl = (const float*)d_in[2];
    const float* Wr = (const float*)d_in[3];
    const float* att = (const float*)d_in[4];
    const float* bias = (const float*)d_in[5];
    const float* gamma = (const float*)d_in[6];
    const float* beta = (const float*)d_in[7];

    int n = in_sizes[0] / DD;
    int E = in_sizes[1] / 2;
    int Lnum = in_sizes[2] / (DD * DD);

    float *b0p = nullptr, *b1p = nullptr;
    cudaGetSymbolAddress((void**)&b0p, g_b0);
    cudaGetSymbolAddress((void**)&b1p, g_b1);

    const int gemmSmem = 64 * XH_LD * 2 + 64 * W_LD * 2;  // 26624

    static cudaStream_t s2 = nullptr;
    static cudaEvent_t evFork = nullptr, evJoin = nullptr;
    static int attr_set = 0;
    if (!attr_set) {
        cudaFuncSetAttribute(k_gemm, cudaFuncAttributeMaxDynamicSharedMemorySize, gemmSmem);
        cudaFuncSetAttribute(k_agg, cudaFuncAttributePreferredSharedMemoryCarveout, 0);
        cudaStreamCreateWithFlags(&s2, cudaStreamNonBlocking);
        cudaEventCreateWithFlags(&evFork, cudaEventDisableTiming);
        cudaEventCreateWithFlags(&evJoin, cudaEventDisableTiming);
        attr_set = 1;
    }

    int nbScan = (n + SCAN_TILE - 1) / SCAN_TILE;
    const float* cur = x;
    int aggBlocks = (n + 31) / 32;  // 32 nodes per 256-thread block

    for (int i = 0; i < Lnum; i++) {
        if (i == 0) {
            // fork: CSR chain on s2 concurrent with gemm0 on stream 0
            cudaEventRecord(evFork, 0);
            cudaStreamWaitEvent(s2, evFork, 0);
            k_hist<<<(E + 255) / 256, 256, 0, s2>>>(ei, E);
            k_scan1<<<nbScan, SCAN_BLK, 0, s2>>>(n);
            k_degscan<<<1, 512, 0, s2>>>();
            k_degscatter<<<(n + 255) / 256, 256, 0, s2>>>(n);
            k_scatter<<<(E + 255) / 256, 256, 0, s2>>>(ei, E);
            cudaEventRecord(evJoin, s2);
        }

        k_gemm<<<(n + 63) / 64, 256, gemmSmem>>>(cur, Wl + (size_t)i * DD * DD,
                                                 Wr + (size_t)i * DD * DD, n);

        if (i == 0) cudaStreamWaitEvent(0, evJoin, 0);  // join before agg0

        float* outp;
        if (i == Lnum - 1) outp = (float*)d_out;
        else outp = (i & 1) ? b1p : b0p;

        k_agg<<<aggBlocks, 256>>>(cur, att + (size_t)i * DD,
                                  bias + (size_t)i * DD,
                                  gamma + (size_t)i * DD,
                                  beta + (size_t)i * DD,
                                  outp, n);
        cur = outp;
    }
}